// round 6
// baseline (speedup 1.0000x reference)
#include <cuda_runtime.h>
#include <math.h>
#include <stdint.h>

// HashGrid2D, Morton+grid bucketed, fused gather:
//   zero -> hist(ILP4) -> scan(128 blocks, atomic chunk base) -> scatter(ILP4)
//   -> fused gather (block = 32 sorted points x 16 level-warps, smem-staged
//      points, smem transpose, direct coalesced writeback to out[p_orig]).

#define N_LEVELS 16
#define TBITS    19
#define TSIZE    (1u << TBITS)
#define HMASK    (TSIZE - 1u)
#define PRIME_Y  2654435761u

#define MAXN     1048576
#define NBINS    131072          // 17-bit key: (g<<16) | morton16
#define NCHUNK   128             // NBINS / 1024

struct ScaleArr { float s[N_LEVELS]; };

// -------- scratch (static device globals) --------
__device__ int    d_hist[NBINS];
__device__ int    d_counter;
__device__ float4 d_pts[MAXN];   // (x, y, g-as-bits, orig_p-as-bits)

// -------- morton --------
__device__ __forceinline__ unsigned part1by1(unsigned v) {
    v &= 0xffffu;
    v = (v | (v << 8)) & 0x00FF00FFu;
    v = (v | (v << 4)) & 0x0F0F0F0Fu;
    v = (v | (v << 2)) & 0x33333333u;
    v = (v | (v << 1)) & 0x55555555u;
    return v;
}
__device__ __forceinline__ unsigned key17(float xf, float yf, int g) {
    unsigned mx = (unsigned)(xf * 256.0f); if (mx > 255u) mx = 255u;
    unsigned my = (unsigned)(yf * 256.0f); if (my > 255u) my = 255u;
    return (part1by1(mx) | (part1by1(my) << 1)) | ((unsigned)g << 16);
}

// -------- pass 0: zero histogram + counter --------
__global__ void zero_kernel() {
    int t = blockIdx.x * blockDim.x + threadIdx.x;
    if (t < NBINS) d_hist[t] = 0;
    if (t == 0) d_counter = 0;
}

// -------- pass 1: histogram, 4 points per thread --------
__global__ void hist_kernel(const float2* __restrict__ x,
                            const int* __restrict__ gidx, int N) {
    int t  = blockIdx.x * blockDim.x + threadIdx.x;
    int p0 = t * 4;
    if (p0 >= N) return;
    if (p0 + 3 < N) {
        const float4* x4 = (const float4*)x;
        float4 a = __ldg(&x4[t * 2]);
        float4 b = __ldg(&x4[t * 2 + 1]);
        int4   g = __ldg(&((const int4*)gidx)[t]);
        atomicAdd(&d_hist[key17(a.x, a.y, g.x)], 1);
        atomicAdd(&d_hist[key17(a.z, a.w, g.y)], 1);
        atomicAdd(&d_hist[key17(b.x, b.y, g.z)], 1);
        atomicAdd(&d_hist[key17(b.z, b.w, g.w)], 1);
    } else {
        for (int k = 0; k < 4 && p0 + k < N; k++) {
            float2 xy = __ldg(&x[p0 + k]);
            atomicAdd(&d_hist[key17(xy.x, xy.y, __ldg(&gidx[p0 + k]))], 1);
        }
    }
}

// -------- pass 2: per-chunk scan + atomic global base (single kernel) --------
__global__ void __launch_bounds__(1024) scan_kernel() {
    __shared__ int warpsum[32];
    __shared__ int sbase;
    const int tid  = threadIdx.x;
    const int lane = tid & 31;
    const int wid  = tid >> 5;
    const int idx  = blockIdx.x * 1024 + tid;

    const int v = d_hist[idx];
    int incl = v;
    #pragma unroll
    for (int d = 1; d < 32; d <<= 1) {
        int u = __shfl_up_sync(0xffffffffu, incl, d);
        if (lane >= d) incl += u;
    }
    if (lane == 31) warpsum[wid] = incl;
    __syncthreads();
    if (wid == 0) {
        int s = warpsum[lane];
        #pragma unroll
        for (int d = 1; d < 32; d <<= 1) {
            int u = __shfl_up_sync(0xffffffffu, s, d);
            if (lane >= d) s += u;
        }
        warpsum[lane] = s;
    }
    __syncthreads();
    const int inclT = incl + (wid ? warpsum[wid - 1] : 0);
    if (tid == 1023) sbase = atomicAdd(&d_counter, inclT);
    __syncthreads();
    d_hist[idx] = sbase + inclT - v;   // global exclusive offset of this bin
}

// -------- pass 3: scatter into sorted order, 4 points per thread --------
__global__ void scatter_kernel(const float2* __restrict__ x,
                               const int* __restrict__ gidx, int N) {
    int t  = blockIdx.x * blockDim.x + threadIdx.x;
    int p0 = t * 4;
    if (p0 >= N) return;
    float xs[4], ys[4];
    int   gs[4], cnt;
    if (p0 + 3 < N) {
        const float4* x4 = (const float4*)x;
        float4 a = __ldg(&x4[t * 2]);
        float4 b = __ldg(&x4[t * 2 + 1]);
        int4   g = __ldg(&((const int4*)gidx)[t]);
        xs[0]=a.x; ys[0]=a.y; xs[1]=a.z; ys[1]=a.w;
        xs[2]=b.x; ys[2]=b.y; xs[3]=b.z; ys[3]=b.w;
        gs[0]=g.x; gs[1]=g.y; gs[2]=g.z; gs[3]=g.w;
        cnt = 4;
    } else {
        cnt = N - p0;
        for (int k = 0; k < cnt; k++) {
            float2 xy = __ldg(&x[p0 + k]);
            xs[k]=xy.x; ys[k]=xy.y; gs[k]=__ldg(&gidx[p0 + k]);
        }
    }
    #pragma unroll
    for (int k = 0; k < 4; k++) {
        if (k < cnt) {
            unsigned bin = key17(xs[k], ys[k], gs[k]);
            int pos = atomicAdd(&d_hist[bin], 1);
            d_pts[pos] = make_float4(xs[k], ys[k],
                                     __int_as_float(gs[k]),
                                     __int_as_float(p0 + k));
        }
    }
}

// -------- pass 4: fused gather + writeback --------
__global__ void __launch_bounds__(512) fused_gather_kernel(
    const float2* __restrict__ feat, float4* __restrict__ out4,
    int N, ScaleArr sc)
{
    __shared__ float4 spts[32];
    __shared__ float2 smres[N_LEVELS][33];   // [level][point], padded

    const int i0   = blockIdx.x * 32;
    const int warp = threadIdx.x >> 5;       // level
    const int lane = threadIdx.x & 31;       // point within group

    if (warp == 0) {
        const int i = i0 + lane;
        spts[lane] = (i < N) ? d_pts[i] : make_float4(0.f, 0.f, 0.f, 0.f);
    }
    __syncthreads();

    const float4 pt = spts[lane];
    const int    g  = __float_as_int(pt.z);
    const float  s  = sc.s[warp];
    const float px = pt.x * s;
    const float py = pt.y * s;
    const float fx = floorf(px);
    const float fy = floorf(py);
    const float wx = px - fx;
    const float wy = py - fy;
    const unsigned ix = (unsigned)(int)fx;
    const unsigned iy = (unsigned)(int)fy;

    const float2* __restrict__ base =
        feat + ((size_t)(g * N_LEVELS + warp) << TBITS);

    const unsigned hy0 = iy * PRIME_Y;
    const unsigned hy1 = (iy + 1u) * PRIME_Y;
    const unsigned h00 = (ix ^ hy0) & HMASK;
    const unsigned h01 = (ix ^ hy1) & HMASK;

    float2 f00, f10, f01, f11;
    if ((ix & 1u) == 0u) {
        const float4 q0 = __ldg((const float4*)base + (h00 >> 1));
        const float4 q1 = __ldg((const float4*)base + (h01 >> 1));
        if (h00 & 1u) { f00 = make_float2(q0.z, q0.w); f10 = make_float2(q0.x, q0.y); }
        else          { f00 = make_float2(q0.x, q0.y); f10 = make_float2(q0.z, q0.w); }
        if (h01 & 1u) { f01 = make_float2(q1.z, q1.w); f11 = make_float2(q1.x, q1.y); }
        else          { f01 = make_float2(q1.x, q1.y); f11 = make_float2(q1.z, q1.w); }
    } else {
        const unsigned h10 = ((ix + 1u) ^ hy0) & HMASK;
        const unsigned h11 = ((ix + 1u) ^ hy1) & HMASK;
        f00 = __ldg(base + h00);
        f10 = __ldg(base + h10);
        f01 = __ldg(base + h01);
        f11 = __ldg(base + h11);
    }

    const float w00 = (1.0f - wx) * (1.0f - wy);
    const float w10 = wx * (1.0f - wy);
    const float w01 = (1.0f - wx) * wy;
    const float w11 = wx * wy;

    float2 o;
    o.x = w00 * f00.x + w10 * f10.x + w01 * f01.x + w11 * f11.x;
    o.y = w00 * f00.y + w10 * f10.y + w01 * f01.y + w11 * f11.y;

    smres[warp][lane] = o;
    __syncthreads();

    // writeback: 256 threads write float4; point j = t>>3, quad q = t&7
    if (threadIdx.x < 256) {
        const int j = threadIdx.x >> 3;
        const int q = threadIdx.x & 7;
        if (i0 + j < N) {
            const int p_orig = __float_as_int(spts[j].w);
            const float2 a = smres[2 * q][j];
            const float2 b = smres[2 * q + 1][j];
            out4[(size_t)p_orig * 8 + q] = make_float4(a.x, a.y, b.x, b.y);
        }
    }
}

// -------- fallback (N > MAXN): flat paired kernel --------
__global__ void __launch_bounds__(256) hashgrid2d_paired_kernel(
    const float2* __restrict__ x, const float2* __restrict__ feat,
    const int* __restrict__ gidx, float2* __restrict__ out,
    int n_total, ScaleArr sc)
{
    int t = blockIdx.x * blockDim.x + threadIdx.x;
    if (t >= n_total) return;
    int level = t & 15, p = t >> 4;
    float2 xy = __ldg(&x[p]);
    int g = __ldg(&gidx[p]);
    float s = sc.s[level];
    float px = xy.x * s, py = xy.y * s;
    float fx = floorf(px), fy = floorf(py);
    float wx = px - fx, wy = py - fy;
    unsigned ix = (unsigned)(int)fx, iy = (unsigned)(int)fy;
    const float2* __restrict__ base = feat + ((size_t)(g * N_LEVELS + level) << TBITS);
    unsigned hy0 = iy * PRIME_Y, hy1 = (iy + 1u) * PRIME_Y;
    unsigned h00 = (ix ^ hy0) & HMASK, h01 = (ix ^ hy1) & HMASK;
    float2 f00, f10, f01, f11;
    if ((ix & 1u) == 0u) {
        float4 q0 = __ldg((const float4*)base + (h00 >> 1));
        float4 q1 = __ldg((const float4*)base + (h01 >> 1));
        if (h00 & 1u) { f00 = make_float2(q0.z, q0.w); f10 = make_float2(q0.x, q0.y); }
        else          { f00 = make_float2(q0.x, q0.y); f10 = make_float2(q0.z, q0.w); }
        if (h01 & 1u) { f01 = make_float2(q1.z, q1.w); f11 = make_float2(q1.x, q1.y); }
        else          { f01 = make_float2(q1.x, q1.y); f11 = make_float2(q1.z, q1.w); }
    } else {
        unsigned h10 = ((ix + 1u) ^ hy0) & HMASK;
        unsigned h11 = ((ix + 1u) ^ hy1) & HMASK;
        f00 = __ldg(base + h00); f10 = __ldg(base + h10);
        f01 = __ldg(base + h01); f11 = __ldg(base + h11);
    }
    float w00 = (1.0f - wx) * (1.0f - wy), w10 = wx * (1.0f - wy);
    float w01 = (1.0f - wx) * wy,          w11 = wx * wy;
    float2 o;
    o.x = w00 * f00.x + w10 * f10.x + w01 * f01.x + w11 * f11.x;
    o.y = w00 * f00.y + w10 * f10.y + w01 * f01.y + w11 * f11.y;
    out[t] = o;
}

extern "C" void kernel_launch(void* const* d_in, const int* in_sizes, int n_in,
                              void* d_out, int out_size)
{
    const float2* x    = (const float2*)d_in[0];
    const float2* feat = (const float2*)d_in[1];
    const int*    gidx = (const int*)d_in[2];

    int N = in_sizes[0] / 2;

    ScaleArr sc;
    double bw = exp((log(512.0) - log(16.0)) / (double)(N_LEVELS - 1));
    for (int i = 0; i < N_LEVELS; i++) {
        int res = (int)(16.0 * pow(bw, (double)i));
        sc.s[i] = (float)(res - 1);
    }

    if (N > MAXN) {
        int n_total = N * N_LEVELS;
        hashgrid2d_paired_kernel<<<(n_total + 255) / 256, 256>>>(
            x, feat, gidx, (float2*)d_out, n_total, sc);
        return;
    }

    int nquads = (N + 3) / 4;
    zero_kernel<<<NBINS / 256, 256>>>();
    hist_kernel<<<(nquads + 255) / 256, 256>>>(x, gidx, N);
    scan_kernel<<<NCHUNK, 1024>>>();
    scatter_kernel<<<(nquads + 255) / 256, 256>>>(x, gidx, N);

    fused_gather_kernel<<<(N + 31) / 32, 512>>>(feat, (float4*)d_out, N, sc);
}

// round 7
// speedup vs baseline: 1.1063x; 1.1063x over previous
#include <cuda_runtime.h>
#include <math.h>
#include <stdint.h>

// HashGrid2D, Morton(512)+grid bucketed sort, fused gather:
//   zero -> hist(ILP4) -> scan(512 blocks, atomic chunk base) -> scatter(ILP4)
//   -> fused gather: block = 64 sorted points x 16 level-warps (2 iters/warp,
//      results in regs), branch-free float4 gathers, smem transpose,
//      coalesced writeback to out[p_orig].

#define N_LEVELS 16
#define TBITS    19
#define TSIZE    (1u << TBITS)
#define HMASK    (TSIZE - 1u)
#define PRIME_Y  2654435761u

#define MAXN     1048576
#define KEYBITS  19
#define NBINS    (1 << KEYBITS)     // (g<<18) | morton18
#define NCHUNK   (NBINS / 1024)    // 512

#define PPB      64                 // points per gather block
#define GITER    2                  // PPB / 32

struct ScaleArr { float s[N_LEVELS]; };

// -------- scratch (static device globals) --------
__device__ int    d_hist[NBINS];
__device__ int    d_counter;
__device__ float4 d_pts[MAXN];   // (x, y, g-as-bits, orig_p-as-bits)

// -------- morton (9 bits per axis) --------
__device__ __forceinline__ unsigned part1by1(unsigned v) {
    v &= 0xffffu;
    v = (v | (v << 8)) & 0x00FF00FFu;
    v = (v | (v << 4)) & 0x0F0F0F0Fu;
    v = (v | (v << 2)) & 0x33333333u;
    v = (v | (v << 1)) & 0x55555555u;
    return v;
}
__device__ __forceinline__ unsigned key19(float xf, float yf, int g) {
    unsigned mx = (unsigned)(xf * 512.0f); if (mx > 511u) mx = 511u;
    unsigned my = (unsigned)(yf * 512.0f); if (my > 511u) my = 511u;
    return (part1by1(mx) | (part1by1(my) << 1)) | ((unsigned)g << 18);
}

// -------- pass 0: zero histogram + counter --------
__global__ void zero_kernel() {
    int t = blockIdx.x * blockDim.x + threadIdx.x;
    if (t < NBINS) d_hist[t] = 0;
    if (t == 0) d_counter = 0;
}

// -------- pass 1: histogram, 4 points per thread --------
__global__ void hist_kernel(const float2* __restrict__ x,
                            const int* __restrict__ gidx, int N) {
    int t  = blockIdx.x * blockDim.x + threadIdx.x;
    int p0 = t * 4;
    if (p0 >= N) return;
    if (p0 + 3 < N) {
        const float4* x4 = (const float4*)x;
        float4 a = __ldg(&x4[t * 2]);
        float4 b = __ldg(&x4[t * 2 + 1]);
        int4   g = __ldg(&((const int4*)gidx)[t]);
        atomicAdd(&d_hist[key19(a.x, a.y, g.x)], 1);
        atomicAdd(&d_hist[key19(a.z, a.w, g.y)], 1);
        atomicAdd(&d_hist[key19(b.x, b.y, g.z)], 1);
        atomicAdd(&d_hist[key19(b.z, b.w, g.w)], 1);
    } else {
        for (int k = 0; k < 4 && p0 + k < N; k++) {
            float2 xy = __ldg(&x[p0 + k]);
            atomicAdd(&d_hist[key19(xy.x, xy.y, __ldg(&gidx[p0 + k]))], 1);
        }
    }
}

// -------- pass 2: per-chunk scan + atomic global base --------
__global__ void __launch_bounds__(1024) scan_kernel() {
    __shared__ int warpsum[32];
    __shared__ int sbase;
    const int tid  = threadIdx.x;
    const int lane = tid & 31;
    const int wid  = tid >> 5;
    const int idx  = blockIdx.x * 1024 + tid;

    const int v = d_hist[idx];
    int incl = v;
    #pragma unroll
    for (int d = 1; d < 32; d <<= 1) {
        int u = __shfl_up_sync(0xffffffffu, incl, d);
        if (lane >= d) incl += u;
    }
    if (lane == 31) warpsum[wid] = incl;
    __syncthreads();
    if (wid == 0) {
        int s = warpsum[lane];
        #pragma unroll
        for (int d = 1; d < 32; d <<= 1) {
            int u = __shfl_up_sync(0xffffffffu, s, d);
            if (lane >= d) s += u;
        }
        warpsum[lane] = s;
    }
    __syncthreads();
    const int inclT = incl + (wid ? warpsum[wid - 1] : 0);
    if (tid == 1023) sbase = atomicAdd(&d_counter, inclT);
    __syncthreads();
    d_hist[idx] = sbase + inclT - v;
}

// -------- pass 3: scatter into sorted order, 4 points per thread --------
__global__ void scatter_kernel(const float2* __restrict__ x,
                               const int* __restrict__ gidx, int N) {
    int t  = blockIdx.x * blockDim.x + threadIdx.x;
    int p0 = t * 4;
    if (p0 >= N) return;
    float xs[4], ys[4];
    int   gs[4], cnt;
    if (p0 + 3 < N) {
        const float4* x4 = (const float4*)x;
        float4 a = __ldg(&x4[t * 2]);
        float4 b = __ldg(&x4[t * 2 + 1]);
        int4   g = __ldg(&((const int4*)gidx)[t]);
        xs[0]=a.x; ys[0]=a.y; xs[1]=a.z; ys[1]=a.w;
        xs[2]=b.x; ys[2]=b.y; xs[3]=b.z; ys[3]=b.w;
        gs[0]=g.x; gs[1]=g.y; gs[2]=g.z; gs[3]=g.w;
        cnt = 4;
    } else {
        cnt = N - p0;
        for (int k = 0; k < cnt; k++) {
            float2 xy = __ldg(&x[p0 + k]);
            xs[k]=xy.x; ys[k]=xy.y; gs[k]=__ldg(&gidx[p0 + k]);
        }
    }
    #pragma unroll
    for (int k = 0; k < 4; k++) {
        if (k < cnt) {
            unsigned bin = key19(xs[k], ys[k], gs[k]);
            int pos = atomicAdd(&d_hist[bin], 1);
            d_pts[pos] = make_float4(xs[k], ys[k],
                                     __int_as_float(gs[k]),
                                     __int_as_float(p0 + k));
        }
    }
}

// -------- pass 4: fused gather + writeback (64 points/block) --------
__global__ void __launch_bounds__(512) fused_gather_kernel(
    const float2* __restrict__ feat, float4* __restrict__ out4,
    int N, ScaleArr sc)
{
    __shared__ float4 spts[PPB];
    __shared__ float2 smres[N_LEVELS][PPB + 2];

    const int i0   = blockIdx.x * PPB;
    const int warp = threadIdx.x >> 5;       // level
    const int lane = threadIdx.x & 31;

    if (threadIdx.x < PPB) {
        const int i = i0 + threadIdx.x;
        spts[threadIdx.x] = (i < N) ? d_pts[i] : make_float4(0.f, 0.f, 0.f, 0.f);
    }
    __syncthreads();

    const float s = sc.s[warp];

    float2 res[GITER];
    #pragma unroll
    for (int it = 0; it < GITER; it++) {
        const float4 pt = spts[it * 32 + lane];
        const int    g  = __float_as_int(pt.z);
        const float px = pt.x * s;
        const float py = pt.y * s;
        const float fx = floorf(px);
        const float fy = floorf(py);
        const float wx = px - fx;
        const float wy = py - fy;
        const unsigned ix = (unsigned)(int)fx;
        const unsigned iy = (unsigned)(int)fy;

        const float4* __restrict__ base4 =
            (const float4*)(feat + ((size_t)(g * N_LEVELS + warp) << TBITS));

        const unsigned hy0 = iy * PRIME_Y;
        const unsigned hy1 = (iy + 1u) * PRIME_Y;
        const unsigned h00 = ( ix       ^ hy0) & HMASK;
        const unsigned h10 = ((ix + 1u) ^ hy0) & HMASK;
        const unsigned h01 = ( ix       ^ hy1) & HMASK;
        const unsigned h11 = ((ix + 1u) ^ hy1) & HMASK;

        // branch-free: 4 x LDG.128; each float4 holds entries (h&~1, h|1)
        const float4 qa = __ldg(base4 + (h00 >> 1));
        const float4 qb = __ldg(base4 + (h10 >> 1));
        const float4 qc = __ldg(base4 + (h01 >> 1));
        const float4 qd = __ldg(base4 + (h11 >> 1));

        const float2 f00 = (h00 & 1u) ? make_float2(qa.z, qa.w) : make_float2(qa.x, qa.y);
        const float2 f10 = (h10 & 1u) ? make_float2(qb.z, qb.w) : make_float2(qb.x, qb.y);
        const float2 f01 = (h01 & 1u) ? make_float2(qc.z, qc.w) : make_float2(qc.x, qc.y);
        const float2 f11 = (h11 & 1u) ? make_float2(qd.z, qd.w) : make_float2(qd.x, qd.y);

        const float w00 = (1.0f - wx) * (1.0f - wy);
        const float w10 = wx * (1.0f - wy);
        const float w01 = (1.0f - wx) * wy;
        const float w11 = wx * wy;

        res[it].x = w00 * f00.x + w10 * f10.x + w01 * f01.x + w11 * f11.x;
        res[it].y = w00 * f00.y + w10 * f10.y + w01 * f01.y + w11 * f11.y;
    }

    #pragma unroll
    for (int it = 0; it < GITER; it++)
        smres[warp][it * 32 + lane] = res[it];
    __syncthreads();

    // writeback: 512 threads -> 64 points x 8 float4 (one per thread)
    const int j = threadIdx.x >> 3;       // point 0..63
    const int q = threadIdx.x & 7;        // float4 index 0..7
    if (i0 + j < N) {
        const int p_orig = __float_as_int(spts[j].w);
        const float2 a = smres[2 * q][j];
        const float2 b = smres[2 * q + 1][j];
        out4[(size_t)p_orig * 8 + q] = make_float4(a.x, a.y, b.x, b.y);
    }
}

// -------- fallback (N > MAXN): flat paired kernel --------
__global__ void __launch_bounds__(256) hashgrid2d_paired_kernel(
    const float2* __restrict__ x, const float2* __restrict__ feat,
    const int* __restrict__ gidx, float2* __restrict__ out,
    int n_total, ScaleArr sc)
{
    int t = blockIdx.x * blockDim.x + threadIdx.x;
    if (t >= n_total) return;
    int level = t & 15, p = t >> 4;
    float2 xy = __ldg(&x[p]);
    int g = __ldg(&gidx[p]);
    float s = sc.s[level];
    float px = xy.x * s, py = xy.y * s;
    float fx = floorf(px), fy = floorf(py);
    float wx = px - fx, wy = py - fy;
    unsigned ix = (unsigned)(int)fx, iy = (unsigned)(int)fy;
    const float2* __restrict__ base = feat + ((size_t)(g * N_LEVELS + level) << TBITS);
    unsigned hy0 = iy * PRIME_Y, hy1 = (iy + 1u) * PRIME_Y;
    unsigned h00 = (ix ^ hy0) & HMASK, h01 = (ix ^ hy1) & HMASK;
    float2 f00, f10, f01, f11;
    if ((ix & 1u) == 0u) {
        float4 q0 = __ldg((const float4*)base + (h00 >> 1));
        float4 q1 = __ldg((const float4*)base + (h01 >> 1));
        if (h00 & 1u) { f00 = make_float2(q0.z, q0.w); f10 = make_float2(q0.x, q0.y); }
        else          { f00 = make_float2(q0.x, q0.y); f10 = make_float2(q0.z, q0.w); }
        if (h01 & 1u) { f01 = make_float2(q1.z, q1.w); f11 = make_float2(q1.x, q1.y); }
        else          { f01 = make_float2(q1.x, q1.y); f11 = make_float2(q1.z, q1.w); }
    } else {
        unsigned h10 = ((ix + 1u) ^ hy0) & HMASK;
        unsigned h11 = ((ix + 1u) ^ hy1) & HMASK;
        f00 = __ldg(base + h00); f10 = __ldg(base + h10);
        f01 = __ldg(base + h01); f11 = __ldg(base + h11);
    }
    float w00 = (1.0f - wx) * (1.0f - wy), w10 = wx * (1.0f - wy);
    float w01 = (1.0f - wx) * wy,          w11 = wx * wy;
    float2 o;
    o.x = w00 * f00.x + w10 * f10.x + w01 * f01.x + w11 * f11.x;
    o.y = w00 * f00.y + w10 * f10.y + w01 * f01.y + w11 * f11.y;
    out[t] = o;
}

extern "C" void kernel_launch(void* const* d_in, const int* in_sizes, int n_in,
                              void* d_out, int out_size)
{
    const float2* x    = (const float2*)d_in[0];
    const float2* feat = (const float2*)d_in[1];
    const int*    gidx = (const int*)d_in[2];

    int N = in_sizes[0] / 2;

    ScaleArr sc;
    double bw = exp((log(512.0) - log(16.0)) / (double)(N_LEVELS - 1));
    for (int i = 0; i < N_LEVELS; i++) {
        int res = (int)(16.0 * pow(bw, (double)i));
        sc.s[i] = (float)(res - 1);
    }

    if (N > MAXN) {
        int n_total = N * N_LEVELS;
        hashgrid2d_paired_kernel<<<(n_total + 255) / 256, 256>>>(
            x, feat, gidx, (float2*)d_out, n_total, sc);
        return;
    }

    int nquads = (N + 3) / 4;
    zero_kernel<<<NBINS / 256, 256>>>();
    hist_kernel<<<(nquads + 255) / 256, 256>>>(x, gidx, N);
    scan_kernel<<<NCHUNK, 1024>>>();
    scatter_kernel<<<(nquads + 255) / 256, 256>>>(x, gidx, N);

    fused_gather_kernel<<<(N + PPB - 1) / PPB, 512>>>(feat, (float4*)d_out, N, sc);
}

// round 8
// speedup vs baseline: 1.2421x; 1.1227x over previous
#include <cuda_runtime.h>
#include <math.h>
#include <stdint.h>

// HashGrid2D, Morton(512)+grid bucketed sort, fused gather:
//   zero -> hist(ILP8) -> scan(512 blocks, atomic chunk base) -> scatter(ILP8)
//   -> fused gather: block = 128 sorted points x 16 level-warps (4 iters/warp,
//      results in regs), branch-free float4 gathers, smem transpose,
//      coalesced writeback to out[p_orig].

#define N_LEVELS 16
#define TBITS    19
#define TSIZE    (1u << TBITS)
#define HMASK    (TSIZE - 1u)
#define PRIME_Y  2654435761u

#define MAXN     1048576
#define KEYBITS  19
#define NBINS    (1 << KEYBITS)     // (g<<18) | morton18
#define NCHUNK   (NBINS / 1024)     // 512

#define PPB      128                // points per gather block
#define GITER    4                  // PPB / 32

struct ScaleArr { float s[N_LEVELS]; };

// -------- scratch (static device globals) --------
__device__ int    d_hist[NBINS];
__device__ int    d_counter;
__device__ float4 d_pts[MAXN];   // (x, y, g-as-bits, orig_p-as-bits)

// -------- morton (9 bits per axis) --------
__device__ __forceinline__ unsigned part1by1(unsigned v) {
    v &= 0xffffu;
    v = (v | (v << 8)) & 0x00FF00FFu;
    v = (v | (v << 4)) & 0x0F0F0F0Fu;
    v = (v | (v << 2)) & 0x33333333u;
    v = (v | (v << 1)) & 0x55555555u;
    return v;
}
__device__ __forceinline__ unsigned key19(float xf, float yf, int g) {
    unsigned mx = (unsigned)(xf * 512.0f); if (mx > 511u) mx = 511u;
    unsigned my = (unsigned)(yf * 512.0f); if (my > 511u) my = 511u;
    return (part1by1(mx) | (part1by1(my) << 1)) | ((unsigned)g << 18);
}

// -------- pass 0: zero histogram + counter --------
__global__ void zero_kernel() {
    int t = blockIdx.x * blockDim.x + threadIdx.x;
    if (t < NBINS) d_hist[t] = 0;
    if (t == 0) d_counter = 0;
}

// -------- pass 1: histogram, 8 points per thread --------
__global__ void hist_kernel(const float2* __restrict__ x,
                            const int* __restrict__ gidx, int N) {
    int t  = blockIdx.x * blockDim.x + threadIdx.x;
    int p0 = t * 8;
    if (p0 >= N) return;
    if (p0 + 7 < N) {
        const float4* x4 = (const float4*)x;
        const int4*   g4 = (const int4*)gidx;
        float4 a = __ldg(&x4[t * 4]);
        float4 b = __ldg(&x4[t * 4 + 1]);
        float4 c = __ldg(&x4[t * 4 + 2]);
        float4 d = __ldg(&x4[t * 4 + 3]);
        int4   g0 = __ldg(&g4[t * 2]);
        int4   g1 = __ldg(&g4[t * 2 + 1]);
        atomicAdd(&d_hist[key19(a.x, a.y, g0.x)], 1);
        atomicAdd(&d_hist[key19(a.z, a.w, g0.y)], 1);
        atomicAdd(&d_hist[key19(b.x, b.y, g0.z)], 1);
        atomicAdd(&d_hist[key19(b.z, b.w, g0.w)], 1);
        atomicAdd(&d_hist[key19(c.x, c.y, g1.x)], 1);
        atomicAdd(&d_hist[key19(c.z, c.w, g1.y)], 1);
        atomicAdd(&d_hist[key19(d.x, d.y, g1.z)], 1);
        atomicAdd(&d_hist[key19(d.z, d.w, g1.w)], 1);
    } else {
        for (int k = 0; k < 8 && p0 + k < N; k++) {
            float2 xy = __ldg(&x[p0 + k]);
            atomicAdd(&d_hist[key19(xy.x, xy.y, __ldg(&gidx[p0 + k]))], 1);
        }
    }
}

// -------- pass 2: per-chunk scan + atomic global base --------
__global__ void __launch_bounds__(1024) scan_kernel() {
    __shared__ int warpsum[32];
    __shared__ int sbase;
    const int tid  = threadIdx.x;
    const int lane = tid & 31;
    const int wid  = tid >> 5;
    const int idx  = blockIdx.x * 1024 + tid;

    const int v = d_hist[idx];
    int incl = v;
    #pragma unroll
    for (int d = 1; d < 32; d <<= 1) {
        int u = __shfl_up_sync(0xffffffffu, incl, d);
        if (lane >= d) incl += u;
    }
    if (lane == 31) warpsum[wid] = incl;
    __syncthreads();
    if (wid == 0) {
        int s = warpsum[lane];
        #pragma unroll
        for (int d = 1; d < 32; d <<= 1) {
            int u = __shfl_up_sync(0xffffffffu, s, d);
            if (lane >= d) s += u;
        }
        warpsum[lane] = s;
    }
    __syncthreads();
    const int inclT = incl + (wid ? warpsum[wid - 1] : 0);
    if (tid == 1023) sbase = atomicAdd(&d_counter, inclT);
    __syncthreads();
    d_hist[idx] = sbase + inclT - v;
}

// -------- pass 3: scatter into sorted order, 8 points per thread --------
__global__ void scatter_kernel(const float2* __restrict__ x,
                               const int* __restrict__ gidx, int N) {
    int t  = blockIdx.x * blockDim.x + threadIdx.x;
    int p0 = t * 8;
    if (p0 >= N) return;
    if (p0 + 7 < N) {
        const float4* x4 = (const float4*)x;
        const int4*   g4 = (const int4*)gidx;
        float4 xa = __ldg(&x4[t * 4]);
        float4 xb = __ldg(&x4[t * 4 + 1]);
        float4 xc = __ldg(&x4[t * 4 + 2]);
        float4 xd = __ldg(&x4[t * 4 + 3]);
        int4   g0 = __ldg(&g4[t * 2]);
        int4   g1 = __ldg(&g4[t * 2 + 1]);
        float xs[8] = {xa.x, xa.z, xb.x, xb.z, xc.x, xc.z, xd.x, xd.z};
        float ys[8] = {xa.y, xa.w, xb.y, xb.w, xc.y, xc.w, xd.y, xd.w};
        int   gs[8] = {g0.x, g0.y, g0.z, g0.w, g1.x, g1.y, g1.z, g1.w};
        int pos[8];
        #pragma unroll
        for (int k = 0; k < 8; k++)
            pos[k] = atomicAdd(&d_hist[key19(xs[k], ys[k], gs[k])], 1);
        #pragma unroll
        for (int k = 0; k < 8; k++)
            d_pts[pos[k]] = make_float4(xs[k], ys[k],
                                        __int_as_float(gs[k]),
                                        __int_as_float(p0 + k));
    } else {
        for (int k = 0; k < 8 && p0 + k < N; k++) {
            float2 xy = __ldg(&x[p0 + k]);
            int    g  = __ldg(&gidx[p0 + k]);
            int pos = atomicAdd(&d_hist[key19(xy.x, xy.y, g)], 1);
            d_pts[pos] = make_float4(xy.x, xy.y,
                                     __int_as_float(g),
                                     __int_as_float(p0 + k));
        }
    }
}

// -------- pass 4: fused gather + writeback (128 points/block) --------
__global__ void __launch_bounds__(512) fused_gather_kernel(
    const float2* __restrict__ feat, float4* __restrict__ out4,
    int N, ScaleArr sc)
{
    __shared__ float4 spts[PPB];
    __shared__ float2 smres[N_LEVELS][PPB + 2];

    const int i0   = blockIdx.x * PPB;
    const int warp = threadIdx.x >> 5;       // level
    const int lane = threadIdx.x & 31;

    // stage 128 points (4 coalesced float4 loads per staging warp group)
    #pragma unroll
    for (int k = threadIdx.x; k < PPB; k += 512) { }
    if (threadIdx.x < PPB) {
        const int i = i0 + threadIdx.x;
        spts[threadIdx.x] = (i < N) ? d_pts[i] : make_float4(0.f, 0.f, 0.f, 0.f);
    }
    __syncthreads();

    const float s = sc.s[warp];

    float2 res[GITER];
    #pragma unroll
    for (int it = 0; it < GITER; it++) {
        const float4 pt = spts[it * 32 + lane];
        const int    g  = __float_as_int(pt.z);
        const float px = pt.x * s;
        const float py = pt.y * s;
        const float fx = floorf(px);
        const float fy = floorf(py);
        const float wx = px - fx;
        const float wy = py - fy;
        const unsigned ix = (unsigned)(int)fx;
        const unsigned iy = (unsigned)(int)fy;

        const float4* __restrict__ base4 =
            (const float4*)(feat + ((size_t)(g * N_LEVELS + warp) << TBITS));

        const unsigned hy0 = iy * PRIME_Y;
        const unsigned hy1 = (iy + 1u) * PRIME_Y;
        const unsigned h00 = ( ix       ^ hy0) & HMASK;
        const unsigned h10 = ((ix + 1u) ^ hy0) & HMASK;
        const unsigned h01 = ( ix       ^ hy1) & HMASK;
        const unsigned h11 = ((ix + 1u) ^ hy1) & HMASK;

        const float4 qa = __ldg(base4 + (h00 >> 1));
        const float4 qb = __ldg(base4 + (h10 >> 1));
        const float4 qc = __ldg(base4 + (h01 >> 1));
        const float4 qd = __ldg(base4 + (h11 >> 1));

        const float2 f00 = (h00 & 1u) ? make_float2(qa.z, qa.w) : make_float2(qa.x, qa.y);
        const float2 f10 = (h10 & 1u) ? make_float2(qb.z, qb.w) : make_float2(qb.x, qb.y);
        const float2 f01 = (h01 & 1u) ? make_float2(qc.z, qc.w) : make_float2(qc.x, qc.y);
        const float2 f11 = (h11 & 1u) ? make_float2(qd.z, qd.w) : make_float2(qd.x, qd.y);

        const float w00 = (1.0f - wx) * (1.0f - wy);
        const float w10 = wx * (1.0f - wy);
        const float w01 = (1.0f - wx) * wy;
        const float w11 = wx * wy;

        res[it].x = w00 * f00.x + w10 * f10.x + w01 * f01.x + w11 * f11.x;
        res[it].y = w00 * f00.y + w10 * f10.y + w01 * f01.y + w11 * f11.y;
    }

    #pragma unroll
    for (int it = 0; it < GITER; it++)
        smres[warp][it * 32 + lane] = res[it];
    __syncthreads();

    // writeback: 512 threads x 2 rounds -> 128 points x 8 float4
    #pragma unroll
    for (int r = 0; r < 2; r++) {
        const int idx = threadIdx.x + r * 512;
        const int j = idx >> 3;               // point 0..127
        const int q = idx & 7;                // float4 index 0..7
        if (i0 + j < N) {
            const int p_orig = __float_as_int(spts[j].w);
            const float2 a = smres[2 * q][j];
            const float2 b = smres[2 * q + 1][j];
            out4[(size_t)p_orig * 8 + q] = make_float4(a.x, a.y, b.x, b.y);
        }
    }
}

// -------- fallback (N > MAXN): flat paired kernel --------
__global__ void __launch_bounds__(256) hashgrid2d_paired_kernel(
    const float2* __restrict__ x, const float2* __restrict__ feat,
    const int* __restrict__ gidx, float2* __restrict__ out,
    int n_total, ScaleArr sc)
{
    int t = blockIdx.x * blockDim.x + threadIdx.x;
    if (t >= n_total) return;
    int level = t & 15, p = t >> 4;
    float2 xy = __ldg(&x[p]);
    int g = __ldg(&gidx[p]);
    float s = sc.s[level];
    float px = xy.x * s, py = xy.y * s;
    float fx = floorf(px), fy = floorf(py);
    float wx = px - fx, wy = py - fy;
    unsigned ix = (unsigned)(int)fx, iy = (unsigned)(int)fy;
    const float2* __restrict__ base = feat + ((size_t)(g * N_LEVELS + level) << TBITS);
    unsigned hy0 = iy * PRIME_Y, hy1 = (iy + 1u) * PRIME_Y;
    unsigned h00 = (ix ^ hy0) & HMASK, h01 = (ix ^ hy1) & HMASK;
    unsigned h10 = ((ix + 1u) ^ hy0) & HMASK;
    unsigned h11 = ((ix + 1u) ^ hy1) & HMASK;
    const float4* base4 = (const float4*)base;
    float4 qa = __ldg(base4 + (h00 >> 1));
    float4 qb = __ldg(base4 + (h10 >> 1));
    float4 qc = __ldg(base4 + (h01 >> 1));
    float4 qd = __ldg(base4 + (h11 >> 1));
    float2 f00 = (h00 & 1u) ? make_float2(qa.z, qa.w) : make_float2(qa.x, qa.y);
    float2 f10 = (h10 & 1u) ? make_float2(qb.z, qb.w) : make_float2(qb.x, qb.y);
    float2 f01 = (h01 & 1u) ? make_float2(qc.z, qc.w) : make_float2(qc.x, qc.y);
    float2 f11 = (h11 & 1u) ? make_float2(qd.z, qd.w) : make_float2(qd.x, qd.y);
    float w00 = (1.0f - wx) * (1.0f - wy), w10 = wx * (1.0f - wy);
    float w01 = (1.0f - wx) * wy,          w11 = wx * wy;
    float2 o;
    o.x = w00 * f00.x + w10 * f10.x + w01 * f01.x + w11 * f11.x;
    o.y = w00 * f00.y + w10 * f10.y + w01 * f01.y + w11 * f11.y;
    out[t] = o;
}

extern "C" void kernel_launch(void* const* d_in, const int* in_sizes, int n_in,
                              void* d_out, int out_size)
{
    const float2* x    = (const float2*)d_in[0];
    const float2* feat = (const float2*)d_in[1];
    const int*    gidx = (const int*)d_in[2];

    int N = in_sizes[0] / 2;

    ScaleArr sc;
    double bw = exp((log(512.0) - log(16.0)) / (double)(N_LEVELS - 1));
    for (int i = 0; i < N_LEVELS; i++) {
        int res = (int)(16.0 * pow(bw, (double)i));
        sc.s[i] = (float)(res - 1);
    }

    if (N > MAXN) {
        int n_total = N * N_LEVELS;
        hashgrid2d_paired_kernel<<<(n_total + 255) / 256, 256>>>(
            x, feat, gidx, (float2*)d_out, n_total, sc);
        return;
    }

    int nocts = (N + 7) / 8;
    zero_kernel<<<NBINS / 256, 256>>>();
    hist_kernel<<<(nocts + 255) / 256, 256>>>(x, gidx, N);
    scan_kernel<<<NCHUNK, 1024>>>();
    scatter_kernel<<<(nocts + 255) / 256, 256>>>(x, gidx, N);

    fused_gather_kernel<<<(N + PPB - 1) / PPB, 512>>>(feat, (float4*)d_out, N, sc);
}

// round 9
// speedup vs baseline: 1.2694x; 1.0220x over previous
#include <cuda_runtime.h>
#include <math.h>
#include <stdint.h>

// HashGrid2D, Morton(512)+grid bucketed sort, fused gather:
//   zero -> hist(ILP8, saves per-point rank from atomicAdd return)
//        -> scan(counts -> global bases, atomic chunk offset)
//        -> scatter(ILP8, ATOMIC-FREE: pos = base[bin] + rank[p])
//   -> fused gather: block = 128 sorted points x 16 level-warps (4 iters),
//      branch-free float4 gathers, smem transpose, coalesced writeback.

#define N_LEVELS 16
#define TBITS    19
#define TSIZE    (1u << TBITS)
#define HMASK    (TSIZE - 1u)
#define PRIME_Y  2654435761u

#define MAXN     1048576
#define KEYBITS  19
#define NBINS    (1 << KEYBITS)     // (g<<18) | morton18
#define NCHUNK   (NBINS / 1024)     // 512

#define PPB      128                // points per gather block
#define GITER    4                  // PPB / 32

struct ScaleArr { float s[N_LEVELS]; };

// -------- scratch (static device globals) --------
__device__ int    d_hist[NBINS];
__device__ int    d_counter;
__device__ int    d_rank[MAXN];
__device__ float4 d_pts[MAXN];   // (x, y, g-as-bits, orig_p-as-bits)

// -------- morton (9 bits per axis) --------
__device__ __forceinline__ unsigned part1by1(unsigned v) {
    v &= 0xffffu;
    v = (v | (v << 8)) & 0x00FF00FFu;
    v = (v | (v << 4)) & 0x0F0F0F0Fu;
    v = (v | (v << 2)) & 0x33333333u;
    v = (v | (v << 1)) & 0x55555555u;
    return v;
}
__device__ __forceinline__ unsigned key19(float xf, float yf, int g) {
    unsigned mx = (unsigned)(xf * 512.0f); if (mx > 511u) mx = 511u;
    unsigned my = (unsigned)(yf * 512.0f); if (my > 511u) my = 511u;
    return (part1by1(mx) | (part1by1(my) << 1)) | ((unsigned)g << 18);
}

// -------- pass 0: zero histogram + counter --------
__global__ void zero_kernel() {
    int t = blockIdx.x * blockDim.x + threadIdx.x;
    if (t < NBINS) d_hist[t] = 0;
    if (t == 0) d_counter = 0;
}

// -------- pass 1: histogram + rank capture, 8 points per thread --------
__global__ void hist_kernel(const float2* __restrict__ x,
                            const int* __restrict__ gidx, int N) {
    int t  = blockIdx.x * blockDim.x + threadIdx.x;
    int p0 = t * 8;
    if (p0 >= N) return;
    if (p0 + 7 < N) {
        const float4* x4 = (const float4*)x;
        const int4*   g4 = (const int4*)gidx;
        float4 a = __ldg(&x4[t * 4]);
        float4 b = __ldg(&x4[t * 4 + 1]);
        float4 c = __ldg(&x4[t * 4 + 2]);
        float4 d = __ldg(&x4[t * 4 + 3]);
        int4   g0 = __ldg(&g4[t * 2]);
        int4   g1 = __ldg(&g4[t * 2 + 1]);
        float xs[8] = {a.x, a.z, b.x, b.z, c.x, c.z, d.x, d.z};
        float ys[8] = {a.y, a.w, b.y, b.w, c.y, c.w, d.y, d.w};
        int   gs[8] = {g0.x, g0.y, g0.z, g0.w, g1.x, g1.y, g1.z, g1.w};
        int r[8];
        #pragma unroll
        for (int k = 0; k < 8; k++)
            r[k] = atomicAdd(&d_hist[key19(xs[k], ys[k], gs[k])], 1);
        int4* r4 = (int4*)(d_rank + p0);
        r4[0] = make_int4(r[0], r[1], r[2], r[3]);
        r4[1] = make_int4(r[4], r[5], r[6], r[7]);
    } else {
        for (int k = 0; k < 8 && p0 + k < N; k++) {
            float2 xy = __ldg(&x[p0 + k]);
            d_rank[p0 + k] =
                atomicAdd(&d_hist[key19(xy.x, xy.y, __ldg(&gidx[p0 + k]))], 1);
        }
    }
}

// -------- pass 2: per-chunk scan + atomic global base --------
__global__ void __launch_bounds__(1024) scan_kernel() {
    __shared__ int warpsum[32];
    __shared__ int sbase;
    const int tid  = threadIdx.x;
    const int lane = tid & 31;
    const int wid  = tid >> 5;
    const int idx  = blockIdx.x * 1024 + tid;

    const int v = d_hist[idx];
    int incl = v;
    #pragma unroll
    for (int d = 1; d < 32; d <<= 1) {
        int u = __shfl_up_sync(0xffffffffu, incl, d);
        if (lane >= d) incl += u;
    }
    if (lane == 31) warpsum[wid] = incl;
    __syncthreads();
    if (wid == 0) {
        int s = warpsum[lane];
        #pragma unroll
        for (int d = 1; d < 32; d <<= 1) {
            int u = __shfl_up_sync(0xffffffffu, s, d);
            if (lane >= d) s += u;
        }
        warpsum[lane] = s;
    }
    __syncthreads();
    const int inclT = incl + (wid ? warpsum[wid - 1] : 0);
    if (tid == 1023) sbase = atomicAdd(&d_counter, inclT);
    __syncthreads();
    d_hist[idx] = sbase + inclT - v;    // global exclusive base of this bin
}

// -------- pass 3: atomic-free scatter, 8 points per thread --------
__global__ void scatter_kernel(const float2* __restrict__ x,
                               const int* __restrict__ gidx, int N) {
    int t  = blockIdx.x * blockDim.x + threadIdx.x;
    int p0 = t * 8;
    if (p0 >= N) return;
    if (p0 + 7 < N) {
        const float4* x4 = (const float4*)x;
        const int4*   g4 = (const int4*)gidx;
        const int4*   r4 = (const int4*)(d_rank + p0);
        float4 xa = __ldg(&x4[t * 4]);
        float4 xb = __ldg(&x4[t * 4 + 1]);
        float4 xc = __ldg(&x4[t * 4 + 2]);
        float4 xd = __ldg(&x4[t * 4 + 3]);
        int4   g0 = __ldg(&g4[t * 2]);
        int4   g1 = __ldg(&g4[t * 2 + 1]);
        int4   r0 = r4[0];
        int4   r1 = r4[1];
        float xs[8] = {xa.x, xa.z, xb.x, xb.z, xc.x, xc.z, xd.x, xd.z};
        float ys[8] = {xa.y, xa.w, xb.y, xb.w, xc.y, xc.w, xd.y, xd.w};
        int   gs[8] = {g0.x, g0.y, g0.z, g0.w, g1.x, g1.y, g1.z, g1.w};
        int   rs[8] = {r0.x, r0.y, r0.z, r0.w, r1.x, r1.y, r1.z, r1.w};
        int base[8];
        #pragma unroll
        for (int k = 0; k < 8; k++)
            base[k] = __ldg(&d_hist[key19(xs[k], ys[k], gs[k])]);
        #pragma unroll
        for (int k = 0; k < 8; k++)
            d_pts[base[k] + rs[k]] = make_float4(xs[k], ys[k],
                                                 __int_as_float(gs[k]),
                                                 __int_as_float(p0 + k));
    } else {
        for (int k = 0; k < 8 && p0 + k < N; k++) {
            float2 xy = __ldg(&x[p0 + k]);
            int    g  = __ldg(&gidx[p0 + k]);
            int pos = __ldg(&d_hist[key19(xy.x, xy.y, g)]) + d_rank[p0 + k];
            d_pts[pos] = make_float4(xy.x, xy.y,
                                     __int_as_float(g),
                                     __int_as_float(p0 + k));
        }
    }
}

// -------- pass 4: fused gather + writeback (128 points/block) --------
__global__ void __launch_bounds__(512) fused_gather_kernel(
    const float2* __restrict__ feat, float4* __restrict__ out4,
    int N, ScaleArr sc)
{
    __shared__ float4 spts[PPB];
    __shared__ float2 smres[N_LEVELS][PPB + 2];

    const int i0   = blockIdx.x * PPB;
    const int warp = threadIdx.x >> 5;       // level
    const int lane = threadIdx.x & 31;

    if (threadIdx.x < PPB) {
        const int i = i0 + threadIdx.x;
        spts[threadIdx.x] = (i < N) ? d_pts[i] : make_float4(0.f, 0.f, 0.f, 0.f);
    }
    __syncthreads();

    const float s = sc.s[warp];

    #pragma unroll
    for (int it = 0; it < GITER; it++) {
        const float4 pt = spts[it * 32 + lane];
        const int    g  = __float_as_int(pt.z);
        const float px = pt.x * s;
        const float py = pt.y * s;
        const float fx = floorf(px);
        const float fy = floorf(py);
        const float wx = px - fx;
        const float wy = py - fy;
        const unsigned ix = (unsigned)(int)fx;
        const unsigned iy = (unsigned)(int)fy;

        const float4* __restrict__ base4 =
            (const float4*)(feat + ((size_t)(g * N_LEVELS + warp) << TBITS));

        const unsigned hy0 = iy * PRIME_Y;
        const unsigned hy1 = (iy + 1u) * PRIME_Y;
        const unsigned h00 = ( ix       ^ hy0) & HMASK;
        const unsigned h10 = ((ix + 1u) ^ hy0) & HMASK;
        const unsigned h01 = ( ix       ^ hy1) & HMASK;
        const unsigned h11 = ((ix + 1u) ^ hy1) & HMASK;

        const float4 qa = __ldg(base4 + (h00 >> 1));
        const float4 qb = __ldg(base4 + (h10 >> 1));
        const float4 qc = __ldg(base4 + (h01 >> 1));
        const float4 qd = __ldg(base4 + (h11 >> 1));

        const float2 f00 = (h00 & 1u) ? make_float2(qa.z, qa.w) : make_float2(qa.x, qa.y);
        const float2 f10 = (h10 & 1u) ? make_float2(qb.z, qb.w) : make_float2(qb.x, qb.y);
        const float2 f01 = (h01 & 1u) ? make_float2(qc.z, qc.w) : make_float2(qc.x, qc.y);
        const float2 f11 = (h11 & 1u) ? make_float2(qd.z, qd.w) : make_float2(qd.x, qd.y);

        const float w00 = (1.0f - wx) * (1.0f - wy);
        const float w10 = wx * (1.0f - wy);
        const float w01 = (1.0f - wx) * wy;
        const float w11 = wx * wy;

        float2 o;
        o.x = w00 * f00.x + w10 * f10.x + w01 * f01.x + w11 * f11.x;
        o.y = w00 * f00.y + w10 * f10.y + w01 * f01.y + w11 * f11.y;
        smres[warp][it * 32 + lane] = o;
    }
    __syncthreads();

    // writeback: 512 threads x 2 rounds -> 128 points x 8 float4
    #pragma unroll
    for (int r = 0; r < 2; r++) {
        const int idx = threadIdx.x + r * 512;
        const int j = idx >> 3;               // point 0..127
        const int q = idx & 7;                // float4 index 0..7
        if (i0 + j < N) {
            const int p_orig = __float_as_int(spts[j].w);
            const float2 a = smres[2 * q][j];
            const float2 b = smres[2 * q + 1][j];
            out4[(size_t)p_orig * 8 + q] = make_float4(a.x, a.y, b.x, b.y);
        }
    }
}

// -------- fallback (N > MAXN): flat paired kernel --------
__global__ void __launch_bounds__(256) hashgrid2d_paired_kernel(
    const float2* __restrict__ x, const float2* __restrict__ feat,
    const int* __restrict__ gidx, float2* __restrict__ out,
    int n_total, ScaleArr sc)
{
    int t = blockIdx.x * blockDim.x + threadIdx.x;
    if (t >= n_total) return;
    int level = t & 15, p = t >> 4;
    float2 xy = __ldg(&x[p]);
    int g = __ldg(&gidx[p]);
    float s = sc.s[level];
    float px = xy.x * s, py = xy.y * s;
    float fx = floorf(px), fy = floorf(py);
    float wx = px - fx, wy = py - fy;
    unsigned ix = (unsigned)(int)fx, iy = (unsigned)(int)fy;
    const float2* __restrict__ base = feat + ((size_t)(g * N_LEVELS + level) << TBITS);
    unsigned hy0 = iy * PRIME_Y, hy1 = (iy + 1u) * PRIME_Y;
    unsigned h00 = (ix ^ hy0) & HMASK, h01 = (ix ^ hy1) & HMASK;
    unsigned h10 = ((ix + 1u) ^ hy0) & HMASK;
    unsigned h11 = ((ix + 1u) ^ hy1) & HMASK;
    const float4* base4 = (const float4*)base;
    float4 qa = __ldg(base4 + (h00 >> 1));
    float4 qb = __ldg(base4 + (h10 >> 1));
    float4 qc = __ldg(base4 + (h01 >> 1));
    float4 qd = __ldg(base4 + (h11 >> 1));
    float2 f00 = (h00 & 1u) ? make_float2(qa.z, qa.w) : make_float2(qa.x, qa.y);
    float2 f10 = (h10 & 1u) ? make_float2(qb.z, qb.w) : make_float2(qb.x, qb.y);
    float2 f01 = (h01 & 1u) ? make_float2(qc.z, qc.w) : make_float2(qc.x, qc.y);
    float2 f11 = (h11 & 1u) ? make_float2(qd.z, qd.w) : make_float2(qd.x, qd.y);
    float w00 = (1.0f - wx) * (1.0f - wy), w10 = wx * (1.0f - wy);
    float w01 = (1.0f - wx) * wy,          w11 = wx * wy;
    float2 o;
    o.x = w00 * f00.x + w10 * f10.x + w01 * f01.x + w11 * f11.x;
    o.y = w00 * f00.y + w10 * f10.y + w01 * f01.y + w11 * f11.y;
    out[t] = o;
}

extern "C" void kernel_launch(void* const* d_in, const int* in_sizes, int n_in,
                              void* d_out, int out_size)
{
    const float2* x    = (const float2*)d_in[0];
    const float2* feat = (const float2*)d_in[1];
    const int*    gidx = (const int*)d_in[2];

    int N = in_sizes[0] / 2;

    ScaleArr sc;
    double bw = exp((log(512.0) - log(16.0)) / (double)(N_LEVELS - 1));
    for (int i = 0; i < N_LEVELS; i++) {
        int res = (int)(16.0 * pow(bw, (double)i));
        sc.s[i] = (float)(res - 1);
    }

    if (N > MAXN) {
        int n_total = N * N_LEVELS;
        hashgrid2d_paired_kernel<<<(n_total + 255) / 256, 256>>>(
            x, feat, gidx, (float2*)d_out, n_total, sc);
        return;
    }

    int nocts = (N + 7) / 8;
    zero_kernel<<<NBINS / 256, 256>>>();
    hist_kernel<<<(nocts + 255) / 256, 256>>>(x, gidx, N);
    scan_kernel<<<NCHUNK, 1024>>>();
    scatter_kernel<<<(nocts + 255) / 256, 256>>>(x, gidx, N);

    fused_gather_kernel<<<(N + PPB - 1) / PPB, 512>>>(feat, (float4*)d_out, N, sc);
}

// round 10
// speedup vs baseline: 1.3142x; 1.0353x over previous
#include <cuda_runtime.h>
#include <math.h>
#include <stdint.h>

// HashGrid2D, Morton(512)+grid bucketed sort, fused gather:
//   zero(int4) -> hist(ILP4, saves rank from atomicAdd return)
//              -> scan(counts -> global bases, atomic chunk offset)
//              -> scatter(ILP4, atomic-free: pos = base[bin] + rank[p])
//   -> fused gather: block = 128 sorted points x 16 level-warps (4 iters),
//      branch-free float4 gathers, smem transpose, coalesced writeback.

#define N_LEVELS 16
#define TBITS    19
#define TSIZE    (1u << TBITS)
#define HMASK    (TSIZE - 1u)
#define PRIME_Y  2654435761u

#define MAXN     1048576
#define KEYBITS  19
#define NBINS    (1 << KEYBITS)     // (g<<18) | morton18
#define NCHUNK   (NBINS / 1024)     // 512

#define PPB      128                // points per gather block
#define GITER    4                  // PPB / 32

struct ScaleArr { float s[N_LEVELS]; };

// -------- scratch (static device globals) --------
__device__ int    d_hist[NBINS];
__device__ int    d_counter;
__device__ int    d_rank[MAXN];
__device__ float4 d_pts[MAXN];   // (x, y, g-as-bits, orig_p-as-bits)

// -------- morton (9 bits per axis) --------
__device__ __forceinline__ unsigned part1by1(unsigned v) {
    v &= 0xffffu;
    v = (v | (v << 8)) & 0x00FF00FFu;
    v = (v | (v << 4)) & 0x0F0F0F0Fu;
    v = (v | (v << 2)) & 0x33333333u;
    v = (v | (v << 1)) & 0x55555555u;
    return v;
}
__device__ __forceinline__ unsigned key19(float xf, float yf, int g) {
    unsigned mx = (unsigned)(xf * 512.0f); if (mx > 511u) mx = 511u;
    unsigned my = (unsigned)(yf * 512.0f); if (my > 511u) my = 511u;
    return (part1by1(mx) | (part1by1(my) << 1)) | ((unsigned)g << 18);
}

// -------- pass 0: zero histogram + counter (int4 stores) --------
__global__ void zero_kernel() {
    int t = blockIdx.x * blockDim.x + threadIdx.x;
    if (t < NBINS / 4) ((int4*)d_hist)[t] = make_int4(0, 0, 0, 0);
    if (t == 0) d_counter = 0;
}

// -------- pass 1: histogram + rank capture, 4 points per thread --------
__global__ void hist_kernel(const float2* __restrict__ x,
                            const int* __restrict__ gidx, int N) {
    int t  = blockIdx.x * blockDim.x + threadIdx.x;
    int p0 = t * 4;
    if (p0 >= N) return;
    if (p0 + 3 < N) {
        const float4* x4 = (const float4*)x;
        float4 a = __ldg(&x4[t * 2]);
        float4 b = __ldg(&x4[t * 2 + 1]);
        int4   g = __ldg(&((const int4*)gidx)[t]);
        float xs[4] = {a.x, a.z, b.x, b.z};
        float ys[4] = {a.y, a.w, b.y, b.w};
        int   gs[4] = {g.x, g.y, g.z, g.w};
        int r[4];
        #pragma unroll
        for (int k = 0; k < 4; k++)
            r[k] = atomicAdd(&d_hist[key19(xs[k], ys[k], gs[k])], 1);
        ((int4*)(d_rank + p0))[0] = make_int4(r[0], r[1], r[2], r[3]);
    } else {
        for (int k = 0; k < 4 && p0 + k < N; k++) {
            float2 xy = __ldg(&x[p0 + k]);
            d_rank[p0 + k] =
                atomicAdd(&d_hist[key19(xy.x, xy.y, __ldg(&gidx[p0 + k]))], 1);
        }
    }
}

// -------- pass 2: per-chunk scan + atomic global base --------
__global__ void __launch_bounds__(1024) scan_kernel() {
    __shared__ int warpsum[32];
    __shared__ int sbase;
    const int tid  = threadIdx.x;
    const int lane = tid & 31;
    const int wid  = tid >> 5;
    const int idx  = blockIdx.x * 1024 + tid;

    const int v = d_hist[idx];
    int incl = v;
    #pragma unroll
    for (int d = 1; d < 32; d <<= 1) {
        int u = __shfl_up_sync(0xffffffffu, incl, d);
        if (lane >= d) incl += u;
    }
    if (lane == 31) warpsum[wid] = incl;
    __syncthreads();
    if (wid == 0) {
        int s = warpsum[lane];
        #pragma unroll
        for (int d = 1; d < 32; d <<= 1) {
            int u = __shfl_up_sync(0xffffffffu, s, d);
            if (lane >= d) s += u;
        }
        warpsum[lane] = s;
    }
    __syncthreads();
    const int inclT = incl + (wid ? warpsum[wid - 1] : 0);
    if (tid == 1023) sbase = atomicAdd(&d_counter, inclT);
    __syncthreads();
    d_hist[idx] = sbase + inclT - v;    // global exclusive base of this bin
}

// -------- pass 3: atomic-free scatter, 4 points per thread --------
__global__ void scatter_kernel(const float2* __restrict__ x,
                               const int* __restrict__ gidx, int N) {
    int t  = blockIdx.x * blockDim.x + threadIdx.x;
    int p0 = t * 4;
    if (p0 >= N) return;
    if (p0 + 3 < N) {
        const float4* x4 = (const float4*)x;
        float4 xa = __ldg(&x4[t * 2]);
        float4 xb = __ldg(&x4[t * 2 + 1]);
        int4   g  = __ldg(&((const int4*)gidx)[t]);
        int4   r  = ((const int4*)(d_rank + p0))[0];
        float xs[4] = {xa.x, xa.z, xb.x, xb.z};
        float ys[4] = {xa.y, xa.w, xb.y, xb.w};
        int   gs[4] = {g.x, g.y, g.z, g.w};
        int   rs[4] = {r.x, r.y, r.z, r.w};
        int base[4];
        #pragma unroll
        for (int k = 0; k < 4; k++)
            base[k] = __ldg(&d_hist[key19(xs[k], ys[k], gs[k])]);
        #pragma unroll
        for (int k = 0; k < 4; k++)
            d_pts[base[k] + rs[k]] = make_float4(xs[k], ys[k],
                                                 __int_as_float(gs[k]),
                                                 __int_as_float(p0 + k));
    } else {
        for (int k = 0; k < 4 && p0 + k < N; k++) {
            float2 xy = __ldg(&x[p0 + k]);
            int    g  = __ldg(&gidx[p0 + k]);
            int pos = __ldg(&d_hist[key19(xy.x, xy.y, g)]) + d_rank[p0 + k];
            d_pts[pos] = make_float4(xy.x, xy.y,
                                     __int_as_float(g),
                                     __int_as_float(p0 + k));
        }
    }
}

// -------- pass 4: fused gather + writeback (128 points/block) --------
__global__ void __launch_bounds__(512) fused_gather_kernel(
    const float2* __restrict__ feat, float4* __restrict__ out4,
    int N, ScaleArr sc)
{
    __shared__ float4 spts[PPB];
    __shared__ float2 smres[N_LEVELS][PPB + 2];

    const int i0   = blockIdx.x * PPB;
    const int warp = threadIdx.x >> 5;       // level
    const int lane = threadIdx.x & 31;

    if (threadIdx.x < PPB) {
        const int i = i0 + threadIdx.x;
        spts[threadIdx.x] = (i < N) ? d_pts[i] : make_float4(0.f, 0.f, 0.f, 0.f);
    }
    __syncthreads();

    const float s = sc.s[warp];

    #pragma unroll
    for (int it = 0; it < GITER; it++) {
        const float4 pt = spts[it * 32 + lane];
        const int    g  = __float_as_int(pt.z);
        const float px = pt.x * s;
        const float py = pt.y * s;
        const float fx = floorf(px);
        const float fy = floorf(py);
        const float wx = px - fx;
        const float wy = py - fy;
        const unsigned ix = (unsigned)(int)fx;
        const unsigned iy = (unsigned)(int)fy;

        const float4* __restrict__ base4 =
            (const float4*)(feat + ((size_t)(g * N_LEVELS + warp) << TBITS));

        const unsigned hy0 = iy * PRIME_Y;
        const unsigned hy1 = (iy + 1u) * PRIME_Y;
        const unsigned h00 = ( ix       ^ hy0) & HMASK;
        const unsigned h10 = ((ix + 1u) ^ hy0) & HMASK;
        const unsigned h01 = ( ix       ^ hy1) & HMASK;
        const unsigned h11 = ((ix + 1u) ^ hy1) & HMASK;

        const float4 qa = __ldg(base4 + (h00 >> 1));
        const float4 qb = __ldg(base4 + (h10 >> 1));
        const float4 qc = __ldg(base4 + (h01 >> 1));
        const float4 qd = __ldg(base4 + (h11 >> 1));

        const float2 f00 = (h00 & 1u) ? make_float2(qa.z, qa.w) : make_float2(qa.x, qa.y);
        const float2 f10 = (h10 & 1u) ? make_float2(qb.z, qb.w) : make_float2(qb.x, qb.y);
        const float2 f01 = (h01 & 1u) ? make_float2(qc.z, qc.w) : make_float2(qc.x, qc.y);
        const float2 f11 = (h11 & 1u) ? make_float2(qd.z, qd.w) : make_float2(qd.x, qd.y);

        const float w00 = (1.0f - wx) * (1.0f - wy);
        const float w10 = wx * (1.0f - wy);
        const float w01 = (1.0f - wx) * wy;
        const float w11 = wx * wy;

        float2 o;
        o.x = w00 * f00.x + w10 * f10.x + w01 * f01.x + w11 * f11.x;
        o.y = w00 * f00.y + w10 * f10.y + w01 * f01.y + w11 * f11.y;
        smres[warp][it * 32 + lane] = o;
    }
    __syncthreads();

    // writeback: 512 threads x 2 rounds -> 128 points x 8 float4
    #pragma unroll
    for (int r = 0; r < 2; r++) {
        const int idx = threadIdx.x + r * 512;
        const int j = idx >> 3;               // point 0..127
        const int q = idx & 7;                // float4 index 0..7
        if (i0 + j < N) {
            const int p_orig = __float_as_int(spts[j].w);
            const float2 a = smres[2 * q][j];
            const float2 b = smres[2 * q + 1][j];
            out4[(size_t)p_orig * 8 + q] = make_float4(a.x, a.y, b.x, b.y);
        }
    }
}

// -------- fallback (N > MAXN): flat paired kernel --------
__global__ void __launch_bounds__(256) hashgrid2d_paired_kernel(
    const float2* __restrict__ x, const float2* __restrict__ feat,
    const int* __restrict__ gidx, float2* __restrict__ out,
    int n_total, ScaleArr sc)
{
    int t = blockIdx.x * blockDim.x + threadIdx.x;
    if (t >= n_total) return;
    int level = t & 15, p = t >> 4;
    float2 xy = __ldg(&x[p]);
    int g = __ldg(&gidx[p]);
    float s = sc.s[level];
    float px = xy.x * s, py = xy.y * s;
    float fx = floorf(px), fy = floorf(py);
    float wx = px - fx, wy = py - fy;
    unsigned ix = (unsigned)(int)fx, iy = (unsigned)(int)fy;
    const float2* __restrict__ base = feat + ((size_t)(g * N_LEVELS + level) << TBITS);
    unsigned hy0 = iy * PRIME_Y, hy1 = (iy + 1u) * PRIME_Y;
    unsigned h00 = (ix ^ hy0) & HMASK, h01 = (ix ^ hy1) & HMASK;
    unsigned h10 = ((ix + 1u) ^ hy0) & HMASK;
    unsigned h11 = ((ix + 1u) ^ hy1) & HMASK;
    const float4* base4 = (const float4*)base;
    float4 qa = __ldg(base4 + (h00 >> 1));
    float4 qb = __ldg(base4 + (h10 >> 1));
    float4 qc = __ldg(base4 + (h01 >> 1));
    float4 qd = __ldg(base4 + (h11 >> 1));
    float2 f00 = (h00 & 1u) ? make_float2(qa.z, qa.w) : make_float2(qa.x, qa.y);
    float2 f10 = (h10 & 1u) ? make_float2(qb.z, qb.w) : make_float2(qb.x, qb.y);
    float2 f01 = (h01 & 1u) ? make_float2(qc.z, qc.w) : make_float2(qc.x, qc.y);
    float2 f11 = (h11 & 1u) ? make_float2(qd.z, qd.w) : make_float2(qd.x, qd.y);
    float w00 = (1.0f - wx) * (1.0f - wy), w10 = wx * (1.0f - wy);
    float w01 = (1.0f - wx) * wy,          w11 = wx * wy;
    float2 o;
    o.x = w00 * f00.x + w10 * f10.x + w01 * f01.x + w11 * f11.x;
    o.y = w00 * f00.y + w10 * f10.y + w01 * f01.y + w11 * f11.y;
    out[t] = o;
}

extern "C" void kernel_launch(void* const* d_in, const int* in_sizes, int n_in,
                              void* d_out, int out_size)
{
    const float2* x    = (const float2*)d_in[0];
    const float2* feat = (const float2*)d_in[1];
    const int*    gidx = (const int*)d_in[2];

    int N = in_sizes[0] / 2;

    ScaleArr sc;
    double bw = exp((log(512.0) - log(16.0)) / (double)(N_LEVELS - 1));
    for (int i = 0; i < N_LEVELS; i++) {
        int res = (int)(16.0 * pow(bw, (double)i));
        sc.s[i] = (float)(res - 1);
    }

    if (N > MAXN) {
        int n_total = N * N_LEVELS;
        hashgrid2d_paired_kernel<<<(n_total + 255) / 256, 256>>>(
            x, feat, gidx, (float2*)d_out, n_total, sc);
        return;
    }

    int nquads = (N + 3) / 4;
    zero_kernel<<<NBINS / 4 / 256, 256>>>();
    hist_kernel<<<(nquads + 255) / 256, 256>>>(x, gidx, N);
    scan_kernel<<<NCHUNK, 1024>>>();
    scatter_kernel<<<(nquads + 255) / 256, 256>>>(x, gidx, N);

    fused_gather_kernel<<<(N + PPB - 1) / PPB, 512>>>(feat, (float4*)d_out, N, sc);
}

// round 11
// speedup vs baseline: 1.4186x; 1.0795x over previous
#include <cuda_runtime.h>
#include <math.h>
#include <stdint.h>

// HashGrid2D, Morton(512)+grid bucketed sort, fused gather:
//   hist(ILP4, saves rank) -> scan(counts->bases, atomic chunk offset)
//   -> scatter(ILP4, atomic-free) -> fused gather (warp = level x 32 sorted
//      points, predicated XOR-pair float4 loads, smem transpose writeback;
//      also re-zeros d_hist for the next graph replay).

#define N_LEVELS 16
#define TBITS    19
#define TSIZE    (1u << TBITS)
#define HMASK    (TSIZE - 1u)
#define PRIME_Y  2654435761u

#define MAXN     1048576
#define KEYBITS  19
#define NBINS    (1 << KEYBITS)     // (g<<18) | morton18
#define NCHUNK   (NBINS / 1024)     // 512

#define PPB      128                // points per gather block
#define GITER    4                  // PPB / 32

struct ScaleArr { float s[N_LEVELS]; };

// -------- scratch (static device globals; zero-initialized at load) --------
__device__ int    d_hist[NBINS];
__device__ int    d_counter;
__device__ int    d_rank[MAXN];
__device__ float4 d_pts[MAXN];   // (x, y, g-as-bits, orig_p-as-bits)

// -------- morton (9 bits per axis) --------
__device__ __forceinline__ unsigned part1by1(unsigned v) {
    v &= 0xffffu;
    v = (v | (v << 8)) & 0x00FF00FFu;
    v = (v | (v << 4)) & 0x0F0F0F0Fu;
    v = (v | (v << 2)) & 0x33333333u;
    v = (v | (v << 1)) & 0x55555555u;
    return v;
}
__device__ __forceinline__ unsigned key19(float xf, float yf, int g) {
    unsigned mx = (unsigned)(xf * 512.0f); if (mx > 511u) mx = 511u;
    unsigned my = (unsigned)(yf * 512.0f); if (my > 511u) my = 511u;
    return (part1by1(mx) | (part1by1(my) << 1)) | ((unsigned)g << 18);
}

// -------- fallback zero (only when gather grid too small) --------
__global__ void zero_kernel() {
    int t = blockIdx.x * blockDim.x + threadIdx.x;
    if (t < NBINS / 4) ((int4*)d_hist)[t] = make_int4(0, 0, 0, 0);
    if (t == 0) d_counter = 0;
}

// -------- pass 1: histogram + rank capture, 4 points per thread --------
__global__ void hist_kernel(const float2* __restrict__ x,
                            const int* __restrict__ gidx, int N) {
    int t  = blockIdx.x * blockDim.x + threadIdx.x;
    int p0 = t * 4;
    if (p0 >= N) return;
    if (p0 + 3 < N) {
        const float4* x4 = (const float4*)x;
        float4 a = __ldg(&x4[t * 2]);
        float4 b = __ldg(&x4[t * 2 + 1]);
        int4   g = __ldg(&((const int4*)gidx)[t]);
        float xs[4] = {a.x, a.z, b.x, b.z};
        float ys[4] = {a.y, a.w, b.y, b.w};
        int   gs[4] = {g.x, g.y, g.z, g.w};
        int r[4];
        #pragma unroll
        for (int k = 0; k < 4; k++)
            r[k] = atomicAdd(&d_hist[key19(xs[k], ys[k], gs[k])], 1);
        ((int4*)(d_rank + p0))[0] = make_int4(r[0], r[1], r[2], r[3]);
    } else {
        for (int k = 0; k < 4 && p0 + k < N; k++) {
            float2 xy = __ldg(&x[p0 + k]);
            d_rank[p0 + k] =
                atomicAdd(&d_hist[key19(xy.x, xy.y, __ldg(&gidx[p0 + k]))], 1);
        }
    }
}

// -------- pass 2: per-chunk scan + atomic global base --------
__global__ void __launch_bounds__(1024) scan_kernel() {
    __shared__ int warpsum[32];
    __shared__ int sbase;
    const int tid  = threadIdx.x;
    const int lane = tid & 31;
    const int wid  = tid >> 5;
    const int idx  = blockIdx.x * 1024 + tid;

    const int v = d_hist[idx];
    int incl = v;
    #pragma unroll
    for (int d = 1; d < 32; d <<= 1) {
        int u = __shfl_up_sync(0xffffffffu, incl, d);
        if (lane >= d) incl += u;
    }
    if (lane == 31) warpsum[wid] = incl;
    __syncthreads();
    if (wid == 0) {
        int s = warpsum[lane];
        #pragma unroll
        for (int d = 1; d < 32; d <<= 1) {
            int u = __shfl_up_sync(0xffffffffu, s, d);
            if (lane >= d) s += u;
        }
        warpsum[lane] = s;
    }
    __syncthreads();
    const int inclT = incl + (wid ? warpsum[wid - 1] : 0);
    if (tid == 1023) sbase = atomicAdd(&d_counter, inclT);
    __syncthreads();
    d_hist[idx] = sbase + inclT - v;    // global exclusive base of this bin
}

// -------- pass 3: atomic-free scatter, 4 points per thread --------
__global__ void scatter_kernel(const float2* __restrict__ x,
                               const int* __restrict__ gidx, int N) {
    int t  = blockIdx.x * blockDim.x + threadIdx.x;
    int p0 = t * 4;
    if (p0 >= N) return;
    if (p0 + 3 < N) {
        const float4* x4 = (const float4*)x;
        float4 xa = __ldg(&x4[t * 2]);
        float4 xb = __ldg(&x4[t * 2 + 1]);
        int4   g  = __ldg(&((const int4*)gidx)[t]);
        int4   r  = ((const int4*)(d_rank + p0))[0];
        float xs[4] = {xa.x, xa.z, xb.x, xb.z};
        float ys[4] = {xa.y, xa.w, xb.y, xb.w};
        int   gs[4] = {g.x, g.y, g.z, g.w};
        int   rs[4] = {r.x, r.y, r.z, r.w};
        int base[4];
        #pragma unroll
        for (int k = 0; k < 4; k++)
            base[k] = __ldg(&d_hist[key19(xs[k], ys[k], gs[k])]);
        #pragma unroll
        for (int k = 0; k < 4; k++)
            d_pts[base[k] + rs[k]] = make_float4(xs[k], ys[k],
                                                 __int_as_float(gs[k]),
                                                 __int_as_float(p0 + k));
    } else {
        for (int k = 0; k < 4 && p0 + k < N; k++) {
            float2 xy = __ldg(&x[p0 + k]);
            int    g  = __ldg(&gidx[p0 + k]);
            int pos = __ldg(&d_hist[key19(xy.x, xy.y, g)]) + d_rank[p0 + k];
            d_pts[pos] = make_float4(xy.x, xy.y,
                                     __int_as_float(g),
                                     __int_as_float(p0 + k));
        }
    }
}

// -------- pass 4: fused gather + writeback + hist re-zero --------
__global__ void __launch_bounds__(512) fused_gather_kernel(
    const float2* __restrict__ feat, float4* __restrict__ out4,
    int N, ScaleArr sc)
{
    __shared__ float4 spts[PPB];
    __shared__ float2 smres[N_LEVELS][PPB + 2];

    // re-zero d_hist / d_counter for the next invocation (256 * 512 int4 = NBINS)
    if (blockIdx.x < 256) {
        const int z = blockIdx.x * 512 + threadIdx.x;
        ((int4*)d_hist)[z] = make_int4(0, 0, 0, 0);
        if (z == 0) d_counter = 0;
    }

    const int i0   = blockIdx.x * PPB;
    const int warp = threadIdx.x >> 5;       // level
    const int lane = threadIdx.x & 31;

    if (threadIdx.x < PPB) {
        const int i = i0 + threadIdx.x;
        spts[threadIdx.x] = (i < N) ? d_pts[i] : make_float4(0.f, 0.f, 0.f, 0.f);
    }
    __syncthreads();

    const float s = sc.s[warp];

    #pragma unroll
    for (int it = 0; it < GITER; it++) {
        const float4 pt = spts[it * 32 + lane];
        const int    g  = __float_as_int(pt.z);
        const float px = pt.x * s;
        const float py = pt.y * s;
        const float fx = floorf(px);
        const float fy = floorf(py);
        const float wx = px - fx;
        const float wy = py - fy;
        const unsigned ix = (unsigned)(int)fx;
        const unsigned iy = (unsigned)(int)fy;

        const float4* __restrict__ base4 =
            (const float4*)(feat + ((size_t)(g * N_LEVELS + warp) << TBITS));

        const unsigned hy0 = iy * PRIME_Y;
        const unsigned hy1 = (iy + 1u) * PRIME_Y;
        const unsigned h00 = ( ix       ^ hy0) & HMASK;
        const unsigned h10 = ((ix + 1u) ^ hy0) & HMASK;
        const unsigned h01 = ( ix       ^ hy1) & HMASK;
        const unsigned h11 = ((ix + 1u) ^ hy1) & HMASK;

        // Unconditional loads for the (h00,h01) pairs; the (h10,h11) pairs
        // live in the SAME float4 when ix is even (h10 = h00^1), so those
        // loads are predicated on ix odd -> masked lanes emit no sectors.
        const float4 qa = __ldg(base4 + (h00 >> 1));
        const float4 qc = __ldg(base4 + (h01 >> 1));
        float4 qb = qa;
        float4 qd = qc;
        if (ix & 1u) {
            qb = __ldg(base4 + (h10 >> 1));
            qd = __ldg(base4 + (h11 >> 1));
        }

        const float2 f00 = (h00 & 1u) ? make_float2(qa.z, qa.w) : make_float2(qa.x, qa.y);
        const float2 f10 = (h10 & 1u) ? make_float2(qb.z, qb.w) : make_float2(qb.x, qb.y);
        const float2 f01 = (h01 & 1u) ? make_float2(qc.z, qc.w) : make_float2(qc.x, qc.y);
        const float2 f11 = (h11 & 1u) ? make_float2(qd.z, qd.w) : make_float2(qd.x, qd.y);

        const float w00 = (1.0f - wx) * (1.0f - wy);
        const float w10 = wx * (1.0f - wy);
        const float w01 = (1.0f - wx) * wy;
        const float w11 = wx * wy;

        float2 o;
        o.x = w00 * f00.x + w10 * f10.x + w01 * f01.x + w11 * f11.x;
        o.y = w00 * f00.y + w10 * f10.y + w01 * f01.y + w11 * f11.y;
        smres[warp][it * 32 + lane] = o;
    }
    __syncthreads();

    // writeback: 512 threads x 2 rounds -> 128 points x 8 float4
    #pragma unroll
    for (int r = 0; r < 2; r++) {
        const int idx = threadIdx.x + r * 512;
        const int j = idx >> 3;               // point 0..127
        const int q = idx & 7;                // float4 index 0..7
        if (i0 + j < N) {
            const int p_orig = __float_as_int(spts[j].w);
            const float2 a = smres[2 * q][j];
            const float2 b = smres[2 * q + 1][j];
            out4[(size_t)p_orig * 8 + q] = make_float4(a.x, a.y, b.x, b.y);
        }
    }
}

// -------- fallback (N > MAXN): flat paired kernel --------
__global__ void __launch_bounds__(256) hashgrid2d_paired_kernel(
    const float2* __restrict__ x, const float2* __restrict__ feat,
    const int* __restrict__ gidx, float2* __restrict__ out,
    int n_total, ScaleArr sc)
{
    int t = blockIdx.x * blockDim.x + threadIdx.x;
    if (t >= n_total) return;
    int level = t & 15, p = t >> 4;
    float2 xy = __ldg(&x[p]);
    int g = __ldg(&gidx[p]);
    float s = sc.s[level];
    float px = xy.x * s, py = xy.y * s;
    float fx = floorf(px), fy = floorf(py);
    float wx = px - fx, wy = py - fy;
    unsigned ix = (unsigned)(int)fx, iy = (unsigned)(int)fy;
    const float4* base4 = (const float4*)(feat + ((size_t)(g * N_LEVELS + level) << TBITS));
    unsigned hy0 = iy * PRIME_Y, hy1 = (iy + 1u) * PRIME_Y;
    unsigned h00 = (ix ^ hy0) & HMASK, h01 = (ix ^ hy1) & HMASK;
    unsigned h10 = ((ix + 1u) ^ hy0) & HMASK;
    unsigned h11 = ((ix + 1u) ^ hy1) & HMASK;
    float4 qa = __ldg(base4 + (h00 >> 1));
    float4 qc = __ldg(base4 + (h01 >> 1));
    float4 qb = qa, qd = qc;
    if (ix & 1u) {
        qb = __ldg(base4 + (h10 >> 1));
        qd = __ldg(base4 + (h11 >> 1));
    }
    float2 f00 = (h00 & 1u) ? make_float2(qa.z, qa.w) : make_float2(qa.x, qa.y);
    float2 f10 = (h10 & 1u) ? make_float2(qb.z, qb.w) : make_float2(qb.x, qb.y);
    float2 f01 = (h01 & 1u) ? make_float2(qc.z, qc.w) : make_float2(qc.x, qc.y);
    float2 f11 = (h11 & 1u) ? make_float2(qd.z, qd.w) : make_float2(qd.x, qd.y);
    float w00 = (1.0f - wx) * (1.0f - wy), w10 = wx * (1.0f - wy);
    float w01 = (1.0f - wx) * wy,          w11 = wx * wy;
    float2 o;
    o.x = w00 * f00.x + w10 * f10.x + w01 * f01.x + w11 * f11.x;
    o.y = w00 * f00.y + w10 * f10.y + w01 * f01.y + w11 * f11.y;
    out[t] = o;
}

extern "C" void kernel_launch(void* const* d_in, const int* in_sizes, int n_in,
                              void* d_out, int out_size)
{
    const float2* x    = (const float2*)d_in[0];
    const float2* feat = (const float2*)d_in[1];
    const int*    gidx = (const int*)d_in[2];

    int N = in_sizes[0] / 2;

    ScaleArr sc;
    double bw = exp((log(512.0) - log(16.0)) / (double)(N_LEVELS - 1));
    for (int i = 0; i < N_LEVELS; i++) {
        int res = (int)(16.0 * pow(bw, (double)i));
        sc.s[i] = (float)(res - 1);
    }

    if (N > MAXN) {
        int n_total = N * N_LEVELS;
        hashgrid2d_paired_kernel<<<(n_total + 255) / 256, 256>>>(
            x, feat, gidx, (float2*)d_out, n_total, sc);
        return;
    }

    int gblocks = (N + PPB - 1) / PPB;
    // If gather grid can't cover the hist re-zero, do it explicitly.
    if (gblocks < 256)
        zero_kernel<<<NBINS / 4 / 256 + 1, 256>>>();

    int nquads = (N + 3) / 4;
    hist_kernel<<<(nquads + 255) / 256, 256>>>(x, gidx, N);
    scan_kernel<<<NCHUNK, 1024>>>();
    scatter_kernel<<<(nquads + 255) / 256, 256>>>(x, gidx, N);

    fused_gather_kernel<<<gblocks, 512>>>(feat, (float4*)d_out, N, sc);
}

// round 12
// speedup vs baseline: 1.4813x; 1.0442x over previous
#include <cuda_runtime.h>
#include <math.h>
#include <stdint.h>

// HashGrid2D, Morton(512)+grid bucketed sort, fused gather:
//   hist(ILP4, saves rank) -> scan(counts->bases, atomic chunk offset)
//   -> scatter(ILP4, atomic-free) -> fused gather (warp = level x 32 sorted
//      points, 256 pts/block, predicated XOR-pair float4 loads, smem
//      transpose writeback; re-zeros d_hist for the next graph replay).

#define N_LEVELS 16
#define TBITS    19
#define TSIZE    (1u << TBITS)
#define HMASK    (TSIZE - 1u)
#define PRIME_Y  2654435761u

#define MAXN     1048576
#define KEYBITS  19
#define NBINS    (1 << KEYBITS)     // (g<<18) | morton18
#define NCHUNK   (NBINS / 1024)     // 512

#define PPB      256                // points per gather block
#define GITER    8                  // PPB / 32

struct ScaleArr { float s[N_LEVELS]; };

// -------- scratch (static device globals; zero-initialized at load) --------
__device__ int    d_hist[NBINS];
__device__ int    d_counter;
__device__ int    d_rank[MAXN];
__device__ float4 d_pts[MAXN];   // (x, y, g-as-bits, orig_p-as-bits)

// -------- morton (9 bits per axis) --------
__device__ __forceinline__ unsigned part1by1(unsigned v) {
    v &= 0xffffu;
    v = (v | (v << 8)) & 0x00FF00FFu;
    v = (v | (v << 4)) & 0x0F0F0F0Fu;
    v = (v | (v << 2)) & 0x33333333u;
    v = (v | (v << 1)) & 0x55555555u;
    return v;
}
__device__ __forceinline__ unsigned key19(float xf, float yf, int g) {
    unsigned mx = (unsigned)(xf * 512.0f); if (mx > 511u) mx = 511u;
    unsigned my = (unsigned)(yf * 512.0f); if (my > 511u) my = 511u;
    return (part1by1(mx) | (part1by1(my) << 1)) | ((unsigned)g << 18);
}

// -------- fallback zero (only when gather grid too small) --------
__global__ void zero_kernel() {
    int t = blockIdx.x * blockDim.x + threadIdx.x;
    if (t < NBINS / 4) ((int4*)d_hist)[t] = make_int4(0, 0, 0, 0);
    if (t == 0) d_counter = 0;
}

// -------- pass 1: histogram + rank capture, 4 points per thread --------
__global__ void __launch_bounds__(128) hist_kernel(
    const float2* __restrict__ x, const int* __restrict__ gidx, int N) {
    int t  = blockIdx.x * blockDim.x + threadIdx.x;
    int p0 = t * 4;
    if (p0 >= N) return;
    if (p0 + 3 < N) {
        const float4* x4 = (const float4*)x;
        float4 a = __ldg(&x4[t * 2]);
        float4 b = __ldg(&x4[t * 2 + 1]);
        int4   g = __ldg(&((const int4*)gidx)[t]);
        float xs[4] = {a.x, a.z, b.x, b.z};
        float ys[4] = {a.y, a.w, b.y, b.w};
        int   gs[4] = {g.x, g.y, g.z, g.w};
        int r[4];
        #pragma unroll
        for (int k = 0; k < 4; k++)
            r[k] = atomicAdd(&d_hist[key19(xs[k], ys[k], gs[k])], 1);
        ((int4*)(d_rank + p0))[0] = make_int4(r[0], r[1], r[2], r[3]);
    } else {
        for (int k = 0; k < 4 && p0 + k < N; k++) {
            float2 xy = __ldg(&x[p0 + k]);
            d_rank[p0 + k] =
                atomicAdd(&d_hist[key19(xy.x, xy.y, __ldg(&gidx[p0 + k]))], 1);
        }
    }
}

// -------- pass 2: per-chunk scan + atomic global base --------
__global__ void __launch_bounds__(1024) scan_kernel() {
    __shared__ int warpsum[32];
    __shared__ int sbase;
    const int tid  = threadIdx.x;
    const int lane = tid & 31;
    const int wid  = tid >> 5;
    const int idx  = blockIdx.x * 1024 + tid;

    const int v = d_hist[idx];
    int incl = v;
    #pragma unroll
    for (int d = 1; d < 32; d <<= 1) {
        int u = __shfl_up_sync(0xffffffffu, incl, d);
        if (lane >= d) incl += u;
    }
    if (lane == 31) warpsum[wid] = incl;
    __syncthreads();
    if (wid == 0) {
        int s = warpsum[lane];
        #pragma unroll
        for (int d = 1; d < 32; d <<= 1) {
            int u = __shfl_up_sync(0xffffffffu, s, d);
            if (lane >= d) s += u;
        }
        warpsum[lane] = s;
    }
    __syncthreads();
    const int inclT = incl + (wid ? warpsum[wid - 1] : 0);
    if (tid == 1023) sbase = atomicAdd(&d_counter, inclT);
    __syncthreads();
    d_hist[idx] = sbase + inclT - v;    // global exclusive base of this bin
}

// -------- pass 3: atomic-free scatter, 4 points per thread --------
__global__ void __launch_bounds__(128) scatter_kernel(
    const float2* __restrict__ x, const int* __restrict__ gidx, int N) {
    int t  = blockIdx.x * blockDim.x + threadIdx.x;
    int p0 = t * 4;
    if (p0 >= N) return;
    if (p0 + 3 < N) {
        const float4* x4 = (const float4*)x;
        float4 xa = __ldg(&x4[t * 2]);
        float4 xb = __ldg(&x4[t * 2 + 1]);
        int4   g  = __ldg(&((const int4*)gidx)[t]);
        int4   r  = ((const int4*)(d_rank + p0))[0];
        float xs[4] = {xa.x, xa.z, xb.x, xb.z};
        float ys[4] = {xa.y, xa.w, xb.y, xb.w};
        int   gs[4] = {g.x, g.y, g.z, g.w};
        int   rs[4] = {r.x, r.y, r.z, r.w};
        int base[4];
        #pragma unroll
        for (int k = 0; k < 4; k++)
            base[k] = __ldg(&d_hist[key19(xs[k], ys[k], gs[k])]);
        #pragma unroll
        for (int k = 0; k < 4; k++)
            d_pts[base[k] + rs[k]] = make_float4(xs[k], ys[k],
                                                 __int_as_float(gs[k]),
                                                 __int_as_float(p0 + k));
    } else {
        for (int k = 0; k < 4 && p0 + k < N; k++) {
            float2 xy = __ldg(&x[p0 + k]);
            int    g  = __ldg(&gidx[p0 + k]);
            int pos = __ldg(&d_hist[key19(xy.x, xy.y, g)]) + d_rank[p0 + k];
            d_pts[pos] = make_float4(xy.x, xy.y,
                                     __int_as_float(g),
                                     __int_as_float(p0 + k));
        }
    }
}

// -------- pass 4: fused gather + writeback + hist re-zero --------
__global__ void __launch_bounds__(512) fused_gather_kernel(
    const float2* __restrict__ feat, float4* __restrict__ out4,
    int N, ScaleArr sc)
{
    __shared__ float4 spts[PPB];
    __shared__ float2 smres[N_LEVELS][PPB + 2];

    // re-zero d_hist / d_counter for the next invocation (256 * 512 int4 = NBINS)
    if (blockIdx.x < 256) {
        const int z = blockIdx.x * 512 + threadIdx.x;
        ((int4*)d_hist)[z] = make_int4(0, 0, 0, 0);
        if (z == 0) d_counter = 0;
    }

    const int i0   = blockIdx.x * PPB;
    const int warp = threadIdx.x >> 5;       // level
    const int lane = threadIdx.x & 31;

    #pragma unroll
    for (int k = 0; k < PPB / 512 + 1; k++) {
        const int j = threadIdx.x + k * 512;
        if (j < PPB) {
            const int i = i0 + j;
            spts[j] = (i < N) ? d_pts[i] : make_float4(0.f, 0.f, 0.f, 0.f);
        }
    }
    __syncthreads();

    const float s = sc.s[warp];

    #pragma unroll
    for (int it = 0; it < GITER; it++) {
        const float4 pt = spts[it * 32 + lane];
        const int    g  = __float_as_int(pt.z);
        const float px = pt.x * s;
        const float py = pt.y * s;
        const int  ixi = __float2int_rd(px);
        const int  iyi = __float2int_rd(py);
        const float wx = px - (float)ixi;
        const float wy = py - (float)iyi;
        const unsigned ix = (unsigned)ixi;
        const unsigned iy = (unsigned)iyi;

        const float4* __restrict__ base4 =
            (const float4*)(feat + ((size_t)(g * N_LEVELS + warp) << TBITS));

        const unsigned hy0 = iy * PRIME_Y;
        const unsigned hy1 = hy0 + PRIME_Y;
        const unsigned h00 = ( ix       ^ hy0) & HMASK;
        const unsigned h10 = ((ix + 1u) ^ hy0) & HMASK;
        const unsigned h01 = ( ix       ^ hy1) & HMASK;
        const unsigned h11 = ((ix + 1u) ^ hy1) & HMASK;

        // unconditional loads for (h00,h01); when ix even, h10/h11 share the
        // same float4 (h^1) -> second loads predicated on ix odd.
        const float4 qa = __ldg(base4 + (h00 >> 1));
        const float4 qc = __ldg(base4 + (h01 >> 1));
        float4 qb = qa;
        float4 qd = qc;
        if (ix & 1u) {
            qb = __ldg(base4 + (h10 >> 1));
            qd = __ldg(base4 + (h11 >> 1));
        }

        const float2 f00 = (h00 & 1u) ? make_float2(qa.z, qa.w) : make_float2(qa.x, qa.y);
        const float2 f10 = (h10 & 1u) ? make_float2(qb.z, qb.w) : make_float2(qb.x, qb.y);
        const float2 f01 = (h01 & 1u) ? make_float2(qc.z, qc.w) : make_float2(qc.x, qc.y);
        const float2 f11 = (h11 & 1u) ? make_float2(qd.z, qd.w) : make_float2(qd.x, qd.y);

        const float w00 = (1.0f - wx) * (1.0f - wy);
        const float w10 = wx * (1.0f - wy);
        const float w01 = (1.0f - wx) * wy;
        const float w11 = wx * wy;

        float2 o;
        o.x = w00 * f00.x + w10 * f10.x + w01 * f01.x + w11 * f11.x;
        o.y = w00 * f00.y + w10 * f10.y + w01 * f01.y + w11 * f11.y;
        smres[warp][it * 32 + lane] = o;
    }
    __syncthreads();

    // writeback: 512 threads x 4 rounds -> 256 points x 8 float4
    #pragma unroll
    for (int r = 0; r < PPB * 8 / 512; r++) {
        const int idx = threadIdx.x + r * 512;
        const int j = idx >> 3;               // point 0..PPB-1
        const int q = idx & 7;                // float4 index 0..7
        if (i0 + j < N) {
            const int p_orig = __float_as_int(spts[j].w);
            const float2 a = smres[2 * q][j];
            const float2 b = smres[2 * q + 1][j];
            out4[(size_t)p_orig * 8 + q] = make_float4(a.x, a.y, b.x, b.y);
        }
    }
}

// -------- fallback (N > MAXN): flat paired kernel --------
__global__ void __launch_bounds__(256) hashgrid2d_paired_kernel(
    const float2* __restrict__ x, const float2* __restrict__ feat,
    const int* __restrict__ gidx, float2* __restrict__ out,
    int n_total, ScaleArr sc)
{
    int t = blockIdx.x * blockDim.x + threadIdx.x;
    if (t >= n_total) return;
    int level = t & 15, p = t >> 4;
    float2 xy = __ldg(&x[p]);
    int g = __ldg(&gidx[p]);
    float s = sc.s[level];
    float px = xy.x * s, py = xy.y * s;
    int ixi = __float2int_rd(px), iyi = __float2int_rd(py);
    float wx = px - (float)ixi, wy = py - (float)iyi;
    unsigned ix = (unsigned)ixi, iy = (unsigned)iyi;
    const float4* base4 = (const float4*)(feat + ((size_t)(g * N_LEVELS + level) << TBITS));
    unsigned hy0 = iy * PRIME_Y, hy1 = hy0 + PRIME_Y;
    unsigned h00 = (ix ^ hy0) & HMASK, h01 = (ix ^ hy1) & HMASK;
    unsigned h10 = ((ix + 1u) ^ hy0) & HMASK;
    unsigned h11 = ((ix + 1u) ^ hy1) & HMASK;
    float4 qa = __ldg(base4 + (h00 >> 1));
    float4 qc = __ldg(base4 + (h01 >> 1));
    float4 qb = qa, qd = qc;
    if (ix & 1u) {
        qb = __ldg(base4 + (h10 >> 1));
        qd = __ldg(base4 + (h11 >> 1));
    }
    float2 f00 = (h00 & 1u) ? make_float2(qa.z, qa.w) : make_float2(qa.x, qa.y);
    float2 f10 = (h10 & 1u) ? make_float2(qb.z, qb.w) : make_float2(qb.x, qb.y);
    float2 f01 = (h01 & 1u) ? make_float2(qc.z, qc.w) : make_float2(qc.x, qc.y);
    float2 f11 = (h11 & 1u) ? make_float2(qd.z, qd.w) : make_float2(qd.x, qd.y);
    float w00 = (1.0f - wx) * (1.0f - wy), w10 = wx * (1.0f - wy);
    float w01 = (1.0f - wx) * wy,          w11 = wx * wy;
    float2 o;
    o.x = w00 * f00.x + w10 * f10.x + w01 * f01.x + w11 * f11.x;
    o.y = w00 * f00.y + w10 * f10.y + w01 * f01.y + w11 * f11.y;
    out[t] = o;
}

extern "C" void kernel_launch(void* const* d_in, const int* in_sizes, int n_in,
                              void* d_out, int out_size)
{
    const float2* x    = (const float2*)d_in[0];
    const float2* feat = (const float2*)d_in[1];
    const int*    gidx = (const int*)d_in[2];

    int N = in_sizes[0] / 2;

    ScaleArr sc;
    double bw = exp((log(512.0) - log(16.0)) / (double)(N_LEVELS - 1));
    for (int i = 0; i < N_LEVELS; i++) {
        int res = (int)(16.0 * pow(bw, (double)i));
        sc.s[i] = (float)(res - 1);
    }

    if (N > MAXN) {
        int n_total = N * N_LEVELS;
        hashgrid2d_paired_kernel<<<(n_total + 255) / 256, 256>>>(
            x, feat, gidx, (float2*)d_out, n_total, sc);
        return;
    }

    int gblocks = (N + PPB - 1) / PPB;
    if (gblocks < 256)
        zero_kernel<<<NBINS / 4 / 256 + 1, 256>>>();

    int nquads = (N + 3) / 4;
    hist_kernel<<<(nquads + 127) / 128, 128>>>(x, gidx, N);
    scan_kernel<<<NCHUNK, 1024>>>();
    scatter_kernel<<<(nquads + 127) / 128, 128>>>(x, gidx, N);

    fused_gather_kernel<<<gblocks, 512>>>(feat, (float4*)d_out, N, sc);
}

// round 13
// speedup vs baseline: 1.5525x; 1.0481x over previous
#include <cuda_runtime.h>
#include <math.h>
#include <stdint.h>

// HashGrid2D, Morton(512)+grid bucketed sort, fused gather:
//   hist(ILP4, saves rank) -> scan -> scatter(ILP4, atomic-free)
//   -> fused gather: warp = level x 32 sorted points, 256 pts/block,
//      predicated XOR-pair ulonglong2 loads, packed f32x2 lerp blend,
//      level-major smem transpose writeback (__stcs), hist re-zero fused.

#define N_LEVELS 16
#define TBITS    19
#define TSIZE    (1u << TBITS)
#define HMASK    (TSIZE - 1u)
#define PRIME_Y  2654435761u

#define MAXN     1048576
#define KEYBITS  19
#define NBINS    (1 << KEYBITS)
#define NCHUNK   (NBINS / 1024)

#define PPB      256
#define GITER    8

struct ScaleArr { float s[N_LEVELS]; };

__device__ int    d_hist[NBINS];
__device__ int    d_counter;
__device__ int    d_rank[MAXN];
__device__ float4 d_pts[MAXN];

// -------- packed f32x2 helpers (sm_100+) --------
__device__ __forceinline__ unsigned long long f2_sub(unsigned long long a, unsigned long long b) {
    unsigned long long r;
    asm("sub.rn.f32x2 %0, %1, %2;" : "=l"(r) : "l"(a), "l"(b));
    return r;
}
__device__ __forceinline__ unsigned long long f2_fma(unsigned long long a, unsigned long long b, unsigned long long c) {
    unsigned long long r;
    asm("fma.rn.f32x2 %0, %1, %2, %3;" : "=l"(r) : "l"(a), "l"(b), "l"(c));
    return r;
}
__device__ __forceinline__ unsigned long long f2_bcast(float v) {
    unsigned long long r;
    asm("mov.b64 %0, {%1, %1};" : "=l"(r) : "f"(v));
    return r;
}

// -------- morton --------
__device__ __forceinline__ unsigned part1by1(unsigned v) {
    v &= 0xffffu;
    v = (v | (v << 8)) & 0x00FF00FFu;
    v = (v | (v << 4)) & 0x0F0F0F0Fu;
    v = (v | (v << 2)) & 0x33333333u;
    v = (v | (v << 1)) & 0x55555555u;
    return v;
}
__device__ __forceinline__ unsigned key19(float xf, float yf, int g) {
    unsigned mx = (unsigned)(xf * 512.0f); if (mx > 511u) mx = 511u;
    unsigned my = (unsigned)(yf * 512.0f); if (my > 511u) my = 511u;
    return (part1by1(mx) | (part1by1(my) << 1)) | ((unsigned)g << 18);
}

__global__ void zero_kernel() {
    int t = blockIdx.x * blockDim.x + threadIdx.x;
    if (t < NBINS / 4) ((int4*)d_hist)[t] = make_int4(0, 0, 0, 0);
    if (t == 0) d_counter = 0;
}

// -------- pass 1: histogram + rank capture --------
__global__ void __launch_bounds__(128) hist_kernel(
    const float2* __restrict__ x, const int* __restrict__ gidx, int N) {
    int t  = blockIdx.x * blockDim.x + threadIdx.x;
    int p0 = t * 4;
    if (p0 >= N) return;
    if (p0 + 3 < N) {
        const float4* x4 = (const float4*)x;
        float4 a = __ldg(&x4[t * 2]);
        float4 b = __ldg(&x4[t * 2 + 1]);
        int4   g = __ldg(&((const int4*)gidx)[t]);
        float xs[4] = {a.x, a.z, b.x, b.z};
        float ys[4] = {a.y, a.w, b.y, b.w};
        int   gs[4] = {g.x, g.y, g.z, g.w};
        int r[4];
        #pragma unroll
        for (int k = 0; k < 4; k++)
            r[k] = atomicAdd(&d_hist[key19(xs[k], ys[k], gs[k])], 1);
        ((int4*)(d_rank + p0))[0] = make_int4(r[0], r[1], r[2], r[3]);
    } else {
        for (int k = 0; k < 4 && p0 + k < N; k++) {
            float2 xy = __ldg(&x[p0 + k]);
            d_rank[p0 + k] =
                atomicAdd(&d_hist[key19(xy.x, xy.y, __ldg(&gidx[p0 + k]))], 1);
        }
    }
}

// -------- pass 2: per-chunk scan + atomic global base --------
__global__ void __launch_bounds__(1024) scan_kernel() {
    __shared__ int warpsum[32];
    __shared__ int sbase;
    const int tid  = threadIdx.x;
    const int lane = tid & 31;
    const int wid  = tid >> 5;
    const int idx  = blockIdx.x * 1024 + tid;

    const int v = d_hist[idx];
    int incl = v;
    #pragma unroll
    for (int d = 1; d < 32; d <<= 1) {
        int u = __shfl_up_sync(0xffffffffu, incl, d);
        if (lane >= d) incl += u;
    }
    if (lane == 31) warpsum[wid] = incl;
    __syncthreads();
    if (wid == 0) {
        int s = warpsum[lane];
        #pragma unroll
        for (int d = 1; d < 32; d <<= 1) {
            int u = __shfl_up_sync(0xffffffffu, s, d);
            if (lane >= d) s += u;
        }
        warpsum[lane] = s;
    }
    __syncthreads();
    const int inclT = incl + (wid ? warpsum[wid - 1] : 0);
    if (tid == 1023) sbase = atomicAdd(&d_counter, inclT);
    __syncthreads();
    d_hist[idx] = sbase + inclT - v;
}

// -------- pass 3: atomic-free scatter --------
__global__ void __launch_bounds__(128) scatter_kernel(
    const float2* __restrict__ x, const int* __restrict__ gidx, int N) {
    int t  = blockIdx.x * blockDim.x + threadIdx.x;
    int p0 = t * 4;
    if (p0 >= N) return;
    if (p0 + 3 < N) {
        const float4* x4 = (const float4*)x;
        float4 xa = __ldg(&x4[t * 2]);
        float4 xb = __ldg(&x4[t * 2 + 1]);
        int4   g  = __ldg(&((const int4*)gidx)[t]);
        int4   r  = ((const int4*)(d_rank + p0))[0];
        float xs[4] = {xa.x, xa.z, xb.x, xb.z};
        float ys[4] = {xa.y, xa.w, xb.y, xb.w};
        int   gs[4] = {g.x, g.y, g.z, g.w};
        int   rs[4] = {r.x, r.y, r.z, r.w};
        int base[4];
        #pragma unroll
        for (int k = 0; k < 4; k++)
            base[k] = __ldg(&d_hist[key19(xs[k], ys[k], gs[k])]);
        #pragma unroll
        for (int k = 0; k < 4; k++)
            d_pts[base[k] + rs[k]] = make_float4(xs[k], ys[k],
                                                 __int_as_float(gs[k]),
                                                 __int_as_float(p0 + k));
    } else {
        for (int k = 0; k < 4 && p0 + k < N; k++) {
            float2 xy = __ldg(&x[p0 + k]);
            int    g  = __ldg(&gidx[p0 + k]);
            int pos = __ldg(&d_hist[key19(xy.x, xy.y, g)]) + d_rank[p0 + k];
            d_pts[pos] = make_float4(xy.x, xy.y,
                                     __int_as_float(g),
                                     __int_as_float(p0 + k));
        }
    }
}

// -------- pass 4: fused gather + writeback + hist re-zero --------
__global__ void __launch_bounds__(512) fused_gather_kernel(
    const float2* __restrict__ feat, float2* __restrict__ out2,
    int N, ScaleArr sc)
{
    __shared__ float4 spts[PPB];
    __shared__ float2 smres[N_LEVELS][PPB + 2];

    if (blockIdx.x < 256) {
        const int z = blockIdx.x * 512 + threadIdx.x;
        ((int4*)d_hist)[z] = make_int4(0, 0, 0, 0);
        if (z == 0) d_counter = 0;
    }

    const int i0   = blockIdx.x * PPB;
    const int warp = threadIdx.x >> 5;       // level
    const int lane = threadIdx.x & 31;

    #pragma unroll
    for (int k = 0; k < PPB / 512 + 1; k++) {
        const int j = threadIdx.x + k * 512;
        if (j < PPB) {
            const int i = i0 + j;
            spts[j] = (i < N) ? d_pts[i] : make_float4(0.f, 0.f, 0.f, 0.f);
        }
    }
    __syncthreads();

    const float s = sc.s[warp];

    #pragma unroll
    for (int it = 0; it < GITER; it++) {
        const float4 pt = spts[it * 32 + lane];
        const int    g  = __float_as_int(pt.z);
        const float px = pt.x * s;
        const float py = pt.y * s;
        const int  ixi = __float2int_rd(px);
        const int  iyi = __float2int_rd(py);
        const float wx = px - (float)ixi;
        const float wy = py - (float)iyi;
        const unsigned ix = (unsigned)ixi;
        const unsigned iy = (unsigned)iyi;

        const ulonglong2* __restrict__ baseu =
            (const ulonglong2*)(feat + ((size_t)(g * N_LEVELS + warp) << TBITS));

        const unsigned hy0 = iy * PRIME_Y;
        const unsigned hy1 = hy0 + PRIME_Y;
        const unsigned h00 = ( ix       ^ hy0) & HMASK;
        const unsigned h10 = ((ix + 1u) ^ hy0) & HMASK;
        const unsigned h01 = ( ix       ^ hy1) & HMASK;
        const unsigned h11 = ((ix + 1u) ^ hy1) & HMASK;

        const ulonglong2 qa = __ldg(baseu + (h00 >> 1));
        const ulonglong2 qc = __ldg(baseu + (h01 >> 1));
        ulonglong2 qb = qa;
        ulonglong2 qd = qc;
        if (ix & 1u) {
            qb = __ldg(baseu + (h10 >> 1));
            qd = __ldg(baseu + (h11 >> 1));
        }

        const unsigned long long u00 = (h00 & 1u) ? qa.y : qa.x;
        const unsigned long long u10 = (h10 & 1u) ? qb.y : qb.x;
        const unsigned long long u01 = (h01 & 1u) ? qc.y : qc.x;
        const unsigned long long u11 = (h11 & 1u) ? qd.y : qd.x;

        // bilinear via packed-f32x2 lerps
        const unsigned long long wx2 = f2_bcast(wx);
        const unsigned long long wy2 = f2_bcast(wy);
        const unsigned long long fx0 = f2_fma(wx2, f2_sub(u10, u00), u00);
        const unsigned long long fx1 = f2_fma(wx2, f2_sub(u11, u01), u01);
        const unsigned long long o   = f2_fma(wy2, f2_sub(fx1, fx0), fx0);

        float2 of;
        asm("mov.b64 {%0, %1}, %2;" : "=f"(of.x), "=f"(of.y) : "l"(o));
        smres[warp][it * 32 + lane] = of;
    }
    __syncthreads();

    // writeback: level-major lanes; 16 consecutive threads = one point's
    // 128B output line (coalesced STG.64), LDS at 2-way conflict max.
    #pragma unroll
    for (int r = 0; r < PPB * N_LEVELS / 512; r++) {
        const int idx = threadIdx.x + r * 512;
        const int p = idx >> 4;               // point 0..PPB-1
        const int l = idx & 15;               // level
        if (i0 + p < N) {
            const int p_orig = __float_as_int(spts[p].w);
            __stcs(&out2[(size_t)p_orig * N_LEVELS + l], smres[l][p]);
        }
    }
}

// -------- fallback (N > MAXN): flat paired kernel --------
__global__ void __launch_bounds__(256) hashgrid2d_paired_kernel(
    const float2* __restrict__ x, const float2* __restrict__ feat,
    const int* __restrict__ gidx, float2* __restrict__ out,
    int n_total, ScaleArr sc)
{
    int t = blockIdx.x * blockDim.x + threadIdx.x;
    if (t >= n_total) return;
    int level = t & 15, p = t >> 4;
    float2 xy = __ldg(&x[p]);
    int g = __ldg(&gidx[p]);
    float s = sc.s[level];
    float px = xy.x * s, py = xy.y * s;
    int ixi = __float2int_rd(px), iyi = __float2int_rd(py);
    float wx = px - (float)ixi, wy = py - (float)iyi;
    unsigned ix = (unsigned)ixi, iy = (unsigned)iyi;
    const float4* base4 = (const float4*)(feat + ((size_t)(g * N_LEVELS + level) << TBITS));
    unsigned hy0 = iy * PRIME_Y, hy1 = hy0 + PRIME_Y;
    unsigned h00 = (ix ^ hy0) & HMASK, h01 = (ix ^ hy1) & HMASK;
    unsigned h10 = ((ix + 1u) ^ hy0) & HMASK;
    unsigned h11 = ((ix + 1u) ^ hy1) & HMASK;
    float4 qa = __ldg(base4 + (h00 >> 1));
    float4 qc = __ldg(base4 + (h01 >> 1));
    float4 qb = qa, qd = qc;
    if (ix & 1u) {
        qb = __ldg(base4 + (h10 >> 1));
        qd = __ldg(base4 + (h11 >> 1));
    }
    float2 f00 = (h00 & 1u) ? make_float2(qa.z, qa.w) : make_float2(qa.x, qa.y);
    float2 f10 = (h10 & 1u) ? make_float2(qb.z, qb.w) : make_float2(qb.x, qb.y);
    float2 f01 = (h01 & 1u) ? make_float2(qc.z, qc.w) : make_float2(qc.x, qc.y);
    float2 f11 = (h11 & 1u) ? make_float2(qd.z, qd.w) : make_float2(qd.x, qd.y);
    float w00 = (1.0f - wx) * (1.0f - wy), w10 = wx * (1.0f - wy);
    float w01 = (1.0f - wx) * wy,          w11 = wx * wy;
    float2 o;
    o.x = w00 * f00.x + w10 * f10.x + w01 * f01.x + w11 * f11.x;
    o.y = w00 * f00.y + w10 * f10.y + w01 * f01.y + w11 * f11.y;
    out[t] = o;
}

extern "C" void kernel_launch(void* const* d_in, const int* in_sizes, int n_in,
                              void* d_out, int out_size)
{
    const float2* x    = (const float2*)d_in[0];
    const float2* feat = (const float2*)d_in[1];
    const int*    gidx = (const int*)d_in[2];

    int N = in_sizes[0] / 2;

    ScaleArr sc;
    double bw = exp((log(512.0) - log(16.0)) / (double)(N_LEVELS - 1));
    for (int i = 0; i < N_LEVELS; i++) {
        int res = (int)(16.0 * pow(bw, (double)i));
        sc.s[i] = (float)(res - 1);
    }

    if (N > MAXN) {
        int n_total = N * N_LEVELS;
        hashgrid2d_paired_kernel<<<(n_total + 255) / 256, 256>>>(
            x, feat, gidx, (float2*)d_out, n_total, sc);
        return;
    }

    int gblocks = (N + PPB - 1) / PPB;
    if (gblocks < 256)
        zero_kernel<<<NBINS / 4 / 256 + 1, 256>>>();

    int nquads = (N + 3) / 4;
    hist_kernel<<<(nquads + 127) / 128, 128>>>(x, gidx, N);
    scan_kernel<<<NCHUNK, 1024>>>();
    scatter_kernel<<<(nquads + 127) / 128, 128>>>(x, gidx, N);

    fused_gather_kernel<<<gblocks, 512>>>(feat, (float2*)d_out, N, sc);
}

// round 14
// speedup vs baseline: 1.5675x; 1.0096x over previous
#include <cuda_runtime.h>
#include <math.h>
#include <stdint.h>

// HashGrid2D, Morton(512)+grid bucketed sort, fused gather:
//   hist(ILP4, saves rank) -> scan -> scatter(ILP4, atomic-free)
//   -> fused gather: warp = level x 32 sorted points, 256 pts/block,
//      predicated XOR-pair ulonglong2 loads, packed f32x2 lerp blend,
//      conflict-free level-major smem transpose (stride 257), __stcs
//      writeback, hist re-zero fused.

#define N_LEVELS 16
#define TBITS    19
#define TSIZE    (1u << TBITS)
#define HMASK    (TSIZE - 1u)
#define PRIME_Y  2654435761u

#define MAXN     1048576
#define KEYBITS  19
#define NBINS    (1 << KEYBITS)
#define NCHUNK   (NBINS / 1024)

#define PPB      256
#define GITER    8

struct ScaleArr { float s[N_LEVELS]; };

__device__ int    d_hist[NBINS];
__device__ int    d_counter;
__device__ int    d_rank[MAXN];
__device__ float4 d_pts[MAXN];

// -------- packed f32x2 helpers (sm_100+) --------
__device__ __forceinline__ unsigned long long f2_sub(unsigned long long a, unsigned long long b) {
    unsigned long long r;
    asm("sub.rn.f32x2 %0, %1, %2;" : "=l"(r) : "l"(a), "l"(b));
    return r;
}
__device__ __forceinline__ unsigned long long f2_fma(unsigned long long a, unsigned long long b, unsigned long long c) {
    unsigned long long r;
    asm("fma.rn.f32x2 %0, %1, %2, %3;" : "=l"(r) : "l"(a), "l"(b), "l"(c));
    return r;
}
__device__ __forceinline__ unsigned long long f2_bcast(float v) {
    unsigned long long r;
    asm("mov.b64 %0, {%1, %1};" : "=l"(r) : "f"(v));
    return r;
}

// -------- morton --------
__device__ __forceinline__ unsigned part1by1(unsigned v) {
    v &= 0xffffu;
    v = (v | (v << 8)) & 0x00FF00FFu;
    v = (v | (v << 4)) & 0x0F0F0F0Fu;
    v = (v | (v << 2)) & 0x33333333u;
    v = (v | (v << 1)) & 0x55555555u;
    return v;
}
__device__ __forceinline__ unsigned key19(float xf, float yf, int g) {
    unsigned mx = (unsigned)(xf * 512.0f); if (mx > 511u) mx = 511u;
    unsigned my = (unsigned)(yf * 512.0f); if (my > 511u) my = 511u;
    return (part1by1(mx) | (part1by1(my) << 1)) | ((unsigned)g << 18);
}

__global__ void zero_kernel() {
    int t = blockIdx.x * blockDim.x + threadIdx.x;
    if (t < NBINS / 4) ((int4*)d_hist)[t] = make_int4(0, 0, 0, 0);
    if (t == 0) d_counter = 0;
}

// -------- pass 1: histogram + rank capture --------
__global__ void __launch_bounds__(128) hist_kernel(
    const float2* __restrict__ x, const int* __restrict__ gidx, int N) {
    int t  = blockIdx.x * blockDim.x + threadIdx.x;
    int p0 = t * 4;
    if (p0 >= N) return;
    if (p0 + 3 < N) {
        const float4* x4 = (const float4*)x;
        float4 a = __ldg(&x4[t * 2]);
        float4 b = __ldg(&x4[t * 2 + 1]);
        int4   g = __ldg(&((const int4*)gidx)[t]);
        float xs[4] = {a.x, a.z, b.x, b.z};
        float ys[4] = {a.y, a.w, b.y, b.w};
        int   gs[4] = {g.x, g.y, g.z, g.w};
        int r[4];
        #pragma unroll
        for (int k = 0; k < 4; k++)
            r[k] = atomicAdd(&d_hist[key19(xs[k], ys[k], gs[k])], 1);
        ((int4*)(d_rank + p0))[0] = make_int4(r[0], r[1], r[2], r[3]);
    } else {
        for (int k = 0; k < 4 && p0 + k < N; k++) {
            float2 xy = __ldg(&x[p0 + k]);
            d_rank[p0 + k] =
                atomicAdd(&d_hist[key19(xy.x, xy.y, __ldg(&gidx[p0 + k]))], 1);
        }
    }
}

// -------- pass 2: per-chunk scan + atomic global base --------
__global__ void __launch_bounds__(1024) scan_kernel() {
    __shared__ int warpsum[32];
    __shared__ int sbase;
    const int tid  = threadIdx.x;
    const int lane = tid & 31;
    const int wid  = tid >> 5;
    const int idx  = blockIdx.x * 1024 + tid;

    const int v = d_hist[idx];
    int incl = v;
    #pragma unroll
    for (int d = 1; d < 32; d <<= 1) {
        int u = __shfl_up_sync(0xffffffffu, incl, d);
        if (lane >= d) incl += u;
    }
    if (lane == 31) warpsum[wid] = incl;
    __syncthreads();
    if (wid == 0) {
        int s = warpsum[lane];
        #pragma unroll
        for (int d = 1; d < 32; d <<= 1) {
            int u = __shfl_up_sync(0xffffffffu, s, d);
            if (lane >= d) s += u;
        }
        warpsum[lane] = s;
    }
    __syncthreads();
    const int inclT = incl + (wid ? warpsum[wid - 1] : 0);
    if (tid == 1023) sbase = atomicAdd(&d_counter, inclT);
    __syncthreads();
    d_hist[idx] = sbase + inclT - v;
}

// -------- pass 3: atomic-free scatter --------
__global__ void __launch_bounds__(128) scatter_kernel(
    const float2* __restrict__ x, const int* __restrict__ gidx, int N) {
    int t  = blockIdx.x * blockDim.x + threadIdx.x;
    int p0 = t * 4;
    if (p0 >= N) return;
    if (p0 + 3 < N) {
        const float4* x4 = (const float4*)x;
        float4 xa = __ldg(&x4[t * 2]);
        float4 xb = __ldg(&x4[t * 2 + 1]);
        int4   g  = __ldg(&((const int4*)gidx)[t]);
        int4   r  = ((const int4*)(d_rank + p0))[0];
        float xs[4] = {xa.x, xa.z, xb.x, xb.z};
        float ys[4] = {xa.y, xa.w, xb.y, xb.w};
        int   gs[4] = {g.x, g.y, g.z, g.w};
        int   rs[4] = {r.x, r.y, r.z, r.w};
        int base[4];
        #pragma unroll
        for (int k = 0; k < 4; k++)
            base[k] = __ldg(&d_hist[key19(xs[k], ys[k], gs[k])]);
        #pragma unroll
        for (int k = 0; k < 4; k++)
            d_pts[base[k] + rs[k]] = make_float4(xs[k], ys[k],
                                                 __int_as_float(gs[k]),
                                                 __int_as_float(p0 + k));
    } else {
        for (int k = 0; k < 4 && p0 + k < N; k++) {
            float2 xy = __ldg(&x[p0 + k]);
            int    g  = __ldg(&gidx[p0 + k]);
            int pos = __ldg(&d_hist[key19(xy.x, xy.y, g)]) + d_rank[p0 + k];
            d_pts[pos] = make_float4(xy.x, xy.y,
                                     __int_as_float(g),
                                     __int_as_float(p0 + k));
        }
    }
}

// -------- pass 4: fused gather + writeback + hist re-zero --------
__global__ void __launch_bounds__(512) fused_gather_kernel(
    const float2* __restrict__ feat, float2* __restrict__ out2,
    int N, ScaleArr sc)
{
    __shared__ float4 spts[PPB];
    __shared__ float2 smres[N_LEVELS][PPB + 1];   // 257 f2 = 514 words: conflict-free

    if (blockIdx.x < 256) {
        const int z = blockIdx.x * 512 + threadIdx.x;
        ((int4*)d_hist)[z] = make_int4(0, 0, 0, 0);
        if (z == 0) d_counter = 0;
    }

    const int i0   = blockIdx.x * PPB;
    const int warp = threadIdx.x >> 5;       // level
    const int lane = threadIdx.x & 31;

    #pragma unroll
    for (int k = 0; k < PPB / 512 + 1; k++) {
        const int j = threadIdx.x + k * 512;
        if (j < PPB) {
            const int i = i0 + j;
            spts[j] = (i < N) ? d_pts[i] : make_float4(0.f, 0.f, 0.f, 0.f);
        }
    }
    __syncthreads();

    const float s = sc.s[warp];
    // per-warp table base (g=0); g=1 adds 2^23 float2 (16 tables * 2^19)
    const ulonglong2* __restrict__ warpbase =
        (const ulonglong2*)(feat + ((size_t)warp << TBITS));

    #pragma unroll
    for (int it = 0; it < GITER; it++) {
        const float4 pt = spts[it * 32 + lane];
        const unsigned gbit = __float_as_uint(pt.z);    // 0 or 1
        const float px = pt.x * s;
        const float py = pt.y * s;
        const int  ixi = __float2int_rd(px);
        const int  iyi = __float2int_rd(py);
        const float wx = px - (float)ixi;
        const float wy = py - (float)iyi;
        const unsigned ix = (unsigned)ixi;
        const unsigned iy = (unsigned)iyi;

        const ulonglong2* __restrict__ baseu =
            warpbase + ((size_t)(gbit & 1u) << (23 - 1));  // 2^23 float2 = 2^22 ulonglong2

        const unsigned hy0 = iy * PRIME_Y;
        const unsigned hy1 = hy0 + PRIME_Y;
        const unsigned h00 = ( ix       ^ hy0) & HMASK;
        const unsigned h10 = ((ix + 1u) ^ hy0) & HMASK;
        const unsigned h01 = ( ix       ^ hy1) & HMASK;
        const unsigned h11 = ((ix + 1u) ^ hy1) & HMASK;

        const ulonglong2 qa = __ldg(baseu + (h00 >> 1));
        const ulonglong2 qc = __ldg(baseu + (h01 >> 1));
        ulonglong2 qb = qa;
        ulonglong2 qd = qc;
        if (ix & 1u) {
            qb = __ldg(baseu + (h10 >> 1));
            qd = __ldg(baseu + (h11 >> 1));
        }

        const unsigned long long u00 = (h00 & 1u) ? qa.y : qa.x;
        const unsigned long long u10 = (h10 & 1u) ? qb.y : qb.x;
        const unsigned long long u01 = (h01 & 1u) ? qc.y : qc.x;
        const unsigned long long u11 = (h11 & 1u) ? qd.y : qd.x;

        const unsigned long long wx2 = f2_bcast(wx);
        const unsigned long long wy2 = f2_bcast(wy);
        const unsigned long long fx0 = f2_fma(wx2, f2_sub(u10, u00), u00);
        const unsigned long long fx1 = f2_fma(wx2, f2_sub(u11, u01), u01);
        const unsigned long long o   = f2_fma(wy2, f2_sub(fx1, fx0), fx0);

        float2 of;
        asm("mov.b64 {%0, %1}, %2;" : "=f"(of.x), "=f"(of.y) : "l"(o));
        smres[warp][it * 32 + lane] = of;
    }
    __syncthreads();

    // writeback: level-major lanes; 16 consecutive threads = one point's
    // 128B output line; stride-257 rows -> conflict-free LDS.64.
    #pragma unroll
    for (int r = 0; r < PPB * N_LEVELS / 512; r++) {
        const int idx = threadIdx.x + r * 512;
        const int p = idx >> 4;               // point 0..PPB-1
        const int l = idx & 15;               // level
        if (i0 + p < N) {
            const int p_orig = __float_as_int(spts[p].w);
            __stcs(&out2[(size_t)p_orig * N_LEVELS + l], smres[l][p]);
        }
    }
}

// -------- fallback (N > MAXN): flat paired kernel --------
__global__ void __launch_bounds__(256) hashgrid2d_paired_kernel(
    const float2* __restrict__ x, const float2* __restrict__ feat,
    const int* __restrict__ gidx, float2* __restrict__ out,
    int n_total, ScaleArr sc)
{
    int t = blockIdx.x * blockDim.x + threadIdx.x;
    if (t >= n_total) return;
    int level = t & 15, p = t >> 4;
    float2 xy = __ldg(&x[p]);
    int g = __ldg(&gidx[p]);
    float s = sc.s[level];
    float px = xy.x * s, py = xy.y * s;
    int ixi = __float2int_rd(px), iyi = __float2int_rd(py);
    float wx = px - (float)ixi, wy = py - (float)iyi;
    unsigned ix = (unsigned)ixi, iy = (unsigned)iyi;
    const float4* base4 = (const float4*)(feat + ((size_t)(g * N_LEVELS + level) << TBITS));
    unsigned hy0 = iy * PRIME_Y, hy1 = hy0 + PRIME_Y;
    unsigned h00 = (ix ^ hy0) & HMASK, h01 = (ix ^ hy1) & HMASK;
    unsigned h10 = ((ix + 1u) ^ hy0) & HMASK;
    unsigned h11 = ((ix + 1u) ^ hy1) & HMASK;
    float4 qa = __ldg(base4 + (h00 >> 1));
    float4 qc = __ldg(base4 + (h01 >> 1));
    float4 qb = qa, qd = qc;
    if (ix & 1u) {
        qb = __ldg(base4 + (h10 >> 1));
        qd = __ldg(base4 + (h11 >> 1));
    }
    float2 f00 = (h00 & 1u) ? make_float2(qa.z, qa.w) : make_float2(qa.x, qa.y);
    float2 f10 = (h10 & 1u) ? make_float2(qb.z, qb.w) : make_float2(qb.x, qb.y);
    float2 f01 = (h01 & 1u) ? make_float2(qc.z, qc.w) : make_float2(qc.x, qc.y);
    float2 f11 = (h11 & 1u) ? make_float2(qd.z, qd.w) : make_float2(qd.x, qd.y);
    float w00 = (1.0f - wx) * (1.0f - wy), w10 = wx * (1.0f - wy);
    float w01 = (1.0f - wx) * wy,          w11 = wx * wy;
    float2 o;
    o.x = w00 * f00.x + w10 * f10.x + w01 * f01.x + w11 * f11.x;
    o.y = w00 * f00.y + w10 * f10.y + w01 * f01.y + w11 * f11.y;
    out[t] = o;
}

extern "C" void kernel_launch(void* const* d_in, const int* in_sizes, int n_in,
                              void* d_out, int out_size)
{
    const float2* x    = (const float2*)d_in[0];
    const float2* feat = (const float2*)d_in[1];
    const int*    gidx = (const int*)d_in[2];

    int N = in_sizes[0] / 2;

    ScaleArr sc;
    double bw = exp((log(512.0) - log(16.0)) / (double)(N_LEVELS - 1));
    for (int i = 0; i < N_LEVELS; i++) {
        int res = (int)(16.0 * pow(bw, (double)i));
        sc.s[i] = (float)(res - 1);
    }

    if (N > MAXN) {
        int n_total = N * N_LEVELS;
        hashgrid2d_paired_kernel<<<(n_total + 255) / 256, 256>>>(
            x, feat, gidx, (float2*)d_out, n_total, sc);
        return;
    }

    int gblocks = (N + PPB - 1) / PPB;
    if (gblocks < 256)
        zero_kernel<<<NBINS / 4 / 256 + 1, 256>>>();

    int nquads = (N + 3) / 4;
    hist_kernel<<<(nquads + 127) / 128, 128>>>(x, gidx, N);
    scan_kernel<<<NCHUNK, 1024>>>();
    scatter_kernel<<<(nquads + 127) / 128, 128>>>(x, gidx, N);

    fused_gather_kernel<<<gblocks, 512>>>(feat, (float2*)d_out, N, sc);
}